// round 1
// baseline (speedup 1.0000x reference)
#include <cuda_runtime.h>
#include <math.h>

// ---------------- problem constants ----------------
#define NN   100000
#define EE0  1600000            // raw edges
#define EETOT (EE0 + NN)        // + self loops
#define C1   64                 // in channels
#define H1   4                  // heads layer1
#define D1   32                 // per-head dim layer1
#define HC1  128                // H1*D1
#define OUTC 32                 // layer2 out channels

// ---------------- scratch (device globals; no allocation) ----------------
__device__ float g_h1[NN * HC1];        // layer1 transformed features
__device__ float g_out1[NN * HC1];      // layer1 aggregation (then elu input to layer2)
__device__ float g_al_src1[NN * H1];
__device__ float g_al_dst1[NN * H1];
__device__ int   g_m1[NN * H1];         // ordered-int segment max
__device__ float g_denom1[NN * H1];

__device__ float g_h2[NN * OUTC];
__device__ float g_al_src2[NN];
__device__ float g_al_dst2[NN];
__device__ int   g_m2[NN];
__device__ float g_denom2[NN];

__device__ int   g_is64;                // edge_index element width flag

// ---------------- helpers ----------------
__device__ __forceinline__ int ford(float f) {
    int i = __float_as_int(f);
    return i >= 0 ? i : (i ^ 0x7FFFFFFF);
}
__device__ __forceinline__ float forddec(int i) {
    return __int_as_float(i >= 0 ? i : (i ^ 0x7FFFFFFF));
}
__device__ __forceinline__ float leaky(float v) {
    return v > 0.f ? v : 0.2f * v;
}
// edge_index stored as (2, E). int64 little-endian => int32 view with zero high words.
__device__ __forceinline__ void load_edge(const int* __restrict__ ei, int e, int is64,
                                          int& s, int& d) {
    if (e >= EE0) { s = d = e - EE0; return; }   // self loop
    if (is64) { s = ei[2 * e]; d = ei[2 * (EE0 + e)]; }
    else      { s = ei[e];     d = ei[EE0 + e]; }
}

// ---------------- kernels ----------------
__global__ void detect_kernel(const int* __restrict__ ei) {
    if (blockIdx.x == 0 && threadIdx.x == 0) {
        int zeros = 0;
        for (int i = 0; i < 256; i++) zeros += (ei[2 * i + 1] == 0);
        g_is64 = (zeros == 256) ? 1 : 0;
    }
}

__global__ void init_kernel(float* __restrict__ dout) {
    int i = blockIdx.x * blockDim.x + threadIdx.x;
    int stride = gridDim.x * blockDim.x;
    for (; i < NN * HC1; i += stride) {
        g_out1[i] = 0.f;
        if (i < NN * H1) { g_denom1[i] = 0.f; g_m1[i] = INT_MIN; }
        if (i < NN)      { g_denom2[i] = 0.f; g_m2[i] = INT_MIN; }
        if (i < NN * OUTC) dout[i] = 0.f;
    }
}

// GEMM1: h1[N,128] = x[N,64] @ W1[64,128]
__global__ void gemm1_kernel(const float* __restrict__ x, const float* __restrict__ W) {
    __shared__ float xs[32][C1];       // 8 KB
    __shared__ float Ws[C1][HC1];      // 32 KB
    int tid = threadIdx.x;             // 256
    int row0 = blockIdx.x * 32;
    for (int i = tid; i < C1 * HC1; i += 256) Ws[i / HC1][i % HC1] = W[i];
    for (int i = tid; i < 32 * C1; i += 256) {
        int r = i / C1, k = i % C1;
        int row = row0 + r;
        xs[r][k] = (row < NN) ? x[row * C1 + k] : 0.f;
    }
    __syncthreads();
    int c = tid & 127;
    int rbase = tid >> 7;              // 0 or 1
    float acc[16];
#pragma unroll
    for (int j = 0; j < 16; j++) acc[j] = 0.f;
#pragma unroll
    for (int k = 0; k < C1; k++) {
        float w = Ws[k][c];
#pragma unroll
        for (int j = 0; j < 16; j++) acc[j] += xs[rbase + 2 * j][k] * w;
    }
#pragma unroll
    for (int j = 0; j < 16; j++) {
        int row = row0 + rbase + 2 * j;
        if (row < NN) g_h1[row * HC1 + c] = acc[j];
    }
}

// logits1: warp per node; al_src1/al_dst1 [N,4]
__global__ void logits1_kernel(const float* __restrict__ asrc, const float* __restrict__ adst) {
    int gid = blockIdx.x * blockDim.x + threadIdx.x;
    int node = gid >> 5;
    int lane = gid & 31;
    if (node >= NN) return;
    float4 h = *reinterpret_cast<const float4*>(&g_h1[node * HC1 + lane * 4]);
    float4 a = *reinterpret_cast<const float4*>(&asrc[lane * 4]);
    float4 b = *reinterpret_cast<const float4*>(&adst[lane * 4]);
    float ps = h.x * a.x + h.y * a.y + h.z * a.z + h.w * a.w;
    float pd = h.x * b.x + h.y * b.y + h.z * b.z + h.w * b.w;
#pragma unroll
    for (int off = 4; off >= 1; off >>= 1) {
        ps += __shfl_down_sync(0xffffffffu, ps, off);
        pd += __shfl_down_sync(0xffffffffu, pd, off);
    }
    if ((lane & 7) == 0) {
        int head = lane >> 3;
        g_al_src1[node * H1 + head] = ps;
        g_al_dst1[node * H1 + head] = pd;
    }
}

__global__ void edge_max1_kernel(const int* __restrict__ ei) {
    int e = blockIdx.x * blockDim.x + threadIdx.x;
    if (e >= EETOT) return;
    int is64 = g_is64;
    int s, d; load_edge(ei, e, is64, s, d);
    float4 as = *reinterpret_cast<const float4*>(&g_al_src1[s * H1]);
    float4 ad = *reinterpret_cast<const float4*>(&g_al_dst1[d * H1]);
    float v0 = leaky(as.x + ad.x), v1 = leaky(as.y + ad.y);
    float v2 = leaky(as.z + ad.z), v3 = leaky(as.w + ad.w);
    atomicMax(&g_m1[d * H1 + 0], ford(v0));
    atomicMax(&g_m1[d * H1 + 1], ford(v1));
    atomicMax(&g_m1[d * H1 + 2], ford(v2));
    atomicMax(&g_m1[d * H1 + 3], ford(v3));
}

__global__ void edge_sum1_kernel(const int* __restrict__ ei) {
    int e = blockIdx.x * blockDim.x + threadIdx.x;
    if (e >= EETOT) return;
    int is64 = g_is64;
    int s, d; load_edge(ei, e, is64, s, d);
    float4 as = *reinterpret_cast<const float4*>(&g_al_src1[s * H1]);
    float4 ad = *reinterpret_cast<const float4*>(&g_al_dst1[d * H1]);
    float v[4] = { leaky(as.x + ad.x), leaky(as.y + ad.y),
                   leaky(as.z + ad.z), leaky(as.w + ad.w) };
#pragma unroll
    for (int h = 0; h < H1; h++) {
        float m = forddec(g_m1[d * H1 + h]);
        atomicAdd(&g_denom1[d * H1 + h], __expf(v[h] - m));
    }
}

// warp per edge; 128 channels = 32 lanes x float4
__global__ void edge_agg1_kernel(const int* __restrict__ ei) {
    int gid = blockIdx.x * blockDim.x + threadIdx.x;
    int e = gid >> 5;
    int lane = gid & 31;
    if (e >= EETOT) return;
    int is64 = g_is64;
    int s, d; load_edge(ei, e, is64, s, d);
    float alpha = 0.f;
    if (lane < H1) {
        float v = leaky(g_al_src1[s * H1 + lane] + g_al_dst1[d * H1 + lane]);
        float m = forddec(g_m1[d * H1 + lane]);
        alpha = __expf(v - m) / g_denom1[d * H1 + lane];
    }
    int head = lane >> 3;
    float a = __shfl_sync(0xffffffffu, alpha, head);
    float4 hv = *reinterpret_cast<const float4*>(&g_h1[s * HC1 + lane * 4]);
    float* o = &g_out1[d * HC1 + lane * 4];
    atomicAdd(o + 0, hv.x * a);
    atomicAdd(o + 1, hv.y * a);
    atomicAdd(o + 2, hv.z * a);
    atomicAdd(o + 3, hv.w * a);
}

// GEMM2: h2[N,32] = elu(out1 + b1)[N,128] @ W2[128,32]
__global__ void gemm2_kernel(const float* __restrict__ W, const float* __restrict__ b1) {
    __shared__ float xs[32][HC1];      // 16 KB
    __shared__ float Ws[HC1][OUTC];    // 16 KB
    int tid = threadIdx.x;             // 256
    int row0 = blockIdx.x * 32;
    for (int i = tid; i < HC1 * OUTC; i += 256) Ws[i / OUTC][i % OUTC] = W[i];
    for (int i = tid; i < 32 * HC1; i += 256) {
        int r = i / HC1, k = i % HC1;
        int row = row0 + r;
        float v = 0.f;
        if (row < NN) {
            v = g_out1[row * HC1 + k] + b1[k];
            v = v > 0.f ? v : expm1f(v);       // elu
        }
        xs[r][k] = v;
    }
    __syncthreads();
    int c = tid & 31;
    int rsub = tid >> 5;               // 0..7
    float acc[4] = {0.f, 0.f, 0.f, 0.f};
#pragma unroll
    for (int k = 0; k < HC1; k++) {
        float w = Ws[k][c];
#pragma unroll
        for (int j = 0; j < 4; j++) acc[j] += xs[rsub + 8 * j][k] * w;
    }
#pragma unroll
    for (int j = 0; j < 4; j++) {
        int row = row0 + rsub + 8 * j;
        if (row < NN) g_h2[row * OUTC + c] = acc[j];
    }
}

// logits2: 8 lanes per node
__global__ void logits2_kernel(const float* __restrict__ asrc, const float* __restrict__ adst) {
    int gid = blockIdx.x * blockDim.x + threadIdx.x;
    int node = gid >> 3;
    int sub = gid & 7;
    if (node >= NN) return;
    float4 h = *reinterpret_cast<const float4*>(&g_h2[node * OUTC + sub * 4]);
    float4 a = *reinterpret_cast<const float4*>(&asrc[sub * 4]);
    float4 b = *reinterpret_cast<const float4*>(&adst[sub * 4]);
    float ps = h.x * a.x + h.y * a.y + h.z * a.z + h.w * a.w;
    float pd = h.x * b.x + h.y * b.y + h.z * b.z + h.w * b.w;
#pragma unroll
    for (int off = 4; off >= 1; off >>= 1) {
        ps += __shfl_down_sync(0xffffffffu, ps, off);
        pd += __shfl_down_sync(0xffffffffu, pd, off);
    }
    if (sub == 0) { g_al_src2[node] = ps; g_al_dst2[node] = pd; }
}

__global__ void edge_max2_kernel(const int* __restrict__ ei) {
    int e = blockIdx.x * blockDim.x + threadIdx.x;
    if (e >= EETOT) return;
    int is64 = g_is64;
    int s, d; load_edge(ei, e, is64, s, d);
    float v = leaky(g_al_src2[s] + g_al_dst2[d]);
    atomicMax(&g_m2[d], ford(v));
}

__global__ void edge_sum2_kernel(const int* __restrict__ ei) {
    int e = blockIdx.x * blockDim.x + threadIdx.x;
    if (e >= EETOT) return;
    int is64 = g_is64;
    int s, d; load_edge(ei, e, is64, s, d);
    float v = leaky(g_al_src2[s] + g_al_dst2[d]);
    float m = forddec(g_m2[d]);
    atomicAdd(&g_denom2[d], __expf(v - m));
}

// 4 threads per edge; each covers 8 channels (2 float4)
__global__ void edge_agg2_kernel(const int* __restrict__ ei, float* __restrict__ dout) {
    int gid = blockIdx.x * blockDim.x + threadIdx.x;
    int e = gid >> 2;
    int part = gid & 3;
    if (e >= EETOT) return;
    int is64 = g_is64;
    int s, d; load_edge(ei, e, is64, s, d);
    float v = leaky(g_al_src2[s] + g_al_dst2[d]);
    float m = forddec(g_m2[d]);
    float a = __expf(v - m) / g_denom2[d];
    const float4 h0 = *reinterpret_cast<const float4*>(&g_h2[s * OUTC + part * 8]);
    const float4 h1v = *reinterpret_cast<const float4*>(&g_h2[s * OUTC + part * 8 + 4]);
    float* o = &dout[d * OUTC + part * 8];
    atomicAdd(o + 0, h0.x * a);  atomicAdd(o + 1, h0.y * a);
    atomicAdd(o + 2, h0.z * a);  atomicAdd(o + 3, h0.w * a);
    atomicAdd(o + 4, h1v.x * a); atomicAdd(o + 5, h1v.y * a);
    atomicAdd(o + 6, h1v.z * a); atomicAdd(o + 7, h1v.w * a);
}

__global__ void bias2_kernel(float* __restrict__ dout, const float* __restrict__ b2) {
    int i = blockIdx.x * blockDim.x + threadIdx.x;
    if (i < NN * OUTC) dout[i] += b2[i & (OUTC - 1)];
}

// ---------------- launch ----------------
extern "C" void kernel_launch(void* const* d_in, const int* in_sizes, int n_in,
                              void* d_out, int out_size) {
    const float* x        = (const float*)d_in[0];
    const int*   ei       = (const int*)d_in[1];
    const float* W1       = (const float*)d_in[2];
    const float* att_src1 = (const float*)d_in[3];
    const float* att_dst1 = (const float*)d_in[4];
    const float* b1       = (const float*)d_in[5];
    const float* W2       = (const float*)d_in[6];
    const float* att_src2 = (const float*)d_in[7];
    const float* att_dst2 = (const float*)d_in[8];
    const float* b2       = (const float*)d_in[9];
    float* dout = (float*)d_out;

    const int T = 256;
    detect_kernel<<<1, 32>>>(ei);
    init_kernel<<<2048, T>>>(dout);

    gemm1_kernel<<<(NN + 31) / 32, T>>>(x, W1);
    logits1_kernel<<<(NN * 32 + T - 1) / T, T>>>(att_src1, att_dst1);

    edge_max1_kernel<<<(EETOT + T - 1) / T, T>>>(ei);
    edge_sum1_kernel<<<(EETOT + T - 1) / T, T>>>(ei);
    edge_agg1_kernel<<<((long)EETOT * 32 + T - 1) / T, T>>>(ei);

    gemm2_kernel<<<(NN + 31) / 32, T>>>(W2, b1);
    logits2_kernel<<<(NN * 8 + T - 1) / T, T>>>(att_src2, att_dst2);

    edge_max2_kernel<<<(EETOT + T - 1) / T, T>>>(ei);
    edge_sum2_kernel<<<(EETOT + T - 1) / T, T>>>(ei);
    edge_agg2_kernel<<<(EETOT * 4 + T - 1) / T, T>>>(ei, dout);

    bias2_kernel<<<(NN * OUTC + T - 1) / T, T>>>(dout, b2);
}

// round 2
// speedup vs baseline: 3.4700x; 3.4700x over previous
#include <cuda_runtime.h>
#include <math.h>

// ---------------- problem constants ----------------
#define NN   100000
#define EE0  1600000            // raw edges
#define EETOT (EE0 + NN)        // + self loops
#define C1   64                 // in channels
#define H1   4                  // heads layer1
#define HC1  128                // H1*D1
#define OUTC 32                 // layer2 out channels
#define NB_SCAN 98              // ceil(NN/1024)

// ---------------- scratch (device globals; no allocation) ----------------
__device__ float g_h1[NN * HC1];        // layer1 transformed features
__device__ float g_out1[NN * HC1];      // elu(agg1 + b1)
__device__ float g_al_src1[NN * H1];
__device__ float g_al_dst1[NN * H1];

__device__ float g_h2[NN * OUTC];
__device__ float g_al_src2[NN];
__device__ float g_al_dst2[NN];

// CSR build
__device__ int g_deg[NN];
__device__ int g_cursor[NN];
__device__ int g_scan[NN];
__device__ int g_bsum[NB_SCAN];
__device__ int g_boff[NB_SCAN];
__device__ int g_off[NN + 1];
__device__ int g_esrc[EETOT];

__device__ int g_is64;

// ---------------- helpers ----------------
__device__ __forceinline__ float leaky(float v) { return v > 0.f ? v : 0.2f * v; }

__device__ __forceinline__ void load_edge(const int* __restrict__ ei, int e, int is64,
                                          int& s, int& d) {
    if (e >= EE0) { s = d = e - EE0; return; }
    if (is64) { s = ei[2 * e]; d = ei[2 * (EE0 + e)]; }
    else      { s = ei[e];     d = ei[EE0 + e]; }
}

// ---------------- CSR build ----------------
__global__ void detect_kernel(const int* __restrict__ ei) {
    if (blockIdx.x == 0 && threadIdx.x == 0) {
        int zeros = 0;
        for (int i = 0; i < 256; i++) zeros += (ei[2 * i + 1] == 0);
        g_is64 = (zeros == 256) ? 1 : 0;
    }
}

__global__ void init_kernel() {
    int i = blockIdx.x * blockDim.x + threadIdx.x;
    if (i < NN) { g_deg[i] = 0; g_cursor[i] = 0; }
}

__global__ void hist_kernel(const int* __restrict__ ei) {
    int e = blockIdx.x * blockDim.x + threadIdx.x;
    if (e >= EETOT) return;
    int is64 = g_is64;
    int d;
    if (e >= EE0) d = e - EE0;
    else d = is64 ? ei[2 * (EE0 + e)] : ei[EE0 + e];
    atomicAdd(&g_deg[d], 1);
}

__global__ void scan1_kernel() {
    __shared__ int s[1024];
    int t = threadIdx.x;
    int i = blockIdx.x * 1024 + t;
    int v = (i < NN) ? g_deg[i] : 0;
    s[t] = v;
    __syncthreads();
#pragma unroll
    for (int o = 1; o < 1024; o <<= 1) {
        int u = (t >= o) ? s[t - o] : 0;
        __syncthreads();
        s[t] += u;
        __syncthreads();
    }
    if (i < NN) g_scan[i] = s[t];
    if (t == 1023) g_bsum[blockIdx.x] = s[1023];
}

__global__ void scan2_kernel() {
    __shared__ int s[128];
    int t = threadIdx.x;
    int v = (t < NB_SCAN) ? g_bsum[t] : 0;
    s[t] = v;
    __syncthreads();
#pragma unroll
    for (int o = 1; o < 128; o <<= 1) {
        int u = (t >= o) ? s[t - o] : 0;
        __syncthreads();
        s[t] += u;
        __syncthreads();
    }
    if (t < NB_SCAN) g_boff[t] = s[t] - v;   // exclusive
}

__global__ void scan3_kernel() {
    int i = blockIdx.x * blockDim.x + threadIdx.x;
    if (i == 0) g_off[0] = 0;
    if (i < NN) g_off[i + 1] = g_scan[i] + g_boff[i >> 10];
}

__global__ void scatter_kernel(const int* __restrict__ ei) {
    int e = blockIdx.x * blockDim.x + threadIdx.x;
    if (e >= EETOT) return;
    int is64 = g_is64;
    int s, d;
    load_edge(ei, e, is64, s, d);
    int pos = g_off[d] + atomicAdd(&g_cursor[d], 1);
    g_esrc[pos] = s;
}

// ---------------- GEMM1: h1[N,128] = x[N,64] @ W1[64,128] ----------------
#define G1_ROWS 64
__global__ __launch_bounds__(256) void gemm1_kernel(const float* __restrict__ x,
                                                    const float* __restrict__ W) {
    __shared__ float xst[C1][G1_ROWS];   // [k][row] 16 KB
    __shared__ float Ws[C1][HC1];        // 32 KB
    int tid = threadIdx.x;
    int row0 = blockIdx.x * G1_ROWS;

    const float4* W4 = (const float4*)W;
    float4* Ws4 = (float4*)Ws;
#pragma unroll
    for (int i = 0; i < 8; i++) Ws4[tid + 256 * i] = W4[tid + 256 * i];
#pragma unroll
    for (int i = 0; i < 4; i++) {
        int idx = tid + 256 * i;          // float4 idx; 16 per row
        int r = idx >> 4, k4 = idx & 15;
        int row = row0 + r;
        float4 v = make_float4(0.f, 0.f, 0.f, 0.f);
        if (row < NN) v = *(const float4*)&x[row * C1 + k4 * 4];
        xst[k4 * 4 + 0][r] = v.x; xst[k4 * 4 + 1][r] = v.y;
        xst[k4 * 4 + 2][r] = v.z; xst[k4 * 4 + 3][r] = v.w;
    }
    __syncthreads();

    int lane = tid & 31, w = tid >> 5;
    int rb = w * 8;
    float acc[8][4];
#pragma unroll
    for (int r = 0; r < 8; r++)
#pragma unroll
        for (int c = 0; c < 4; c++) acc[r][c] = 0.f;

#pragma unroll
    for (int k = 0; k < C1; k++) {
        float4 xa = *(float4*)&xst[k][rb];
        float4 xb = *(float4*)&xst[k][rb + 4];
        float4 wv = *(float4*)&Ws[k][lane * 4];
        float xr[8] = {xa.x, xa.y, xa.z, xa.w, xb.x, xb.y, xb.z, xb.w};
#pragma unroll
        for (int r = 0; r < 8; r++) {
            acc[r][0] += xr[r] * wv.x; acc[r][1] += xr[r] * wv.y;
            acc[r][2] += xr[r] * wv.z; acc[r][3] += xr[r] * wv.w;
        }
    }
#pragma unroll
    for (int r = 0; r < 8; r++) {
        int row = row0 + rb + r;
        if (row < NN) *(float4*)&g_h1[row * HC1 + lane * 4] = *(float4*)acc[r];
    }
}

// ---------------- logits1: warp per node ----------------
__global__ void logits1_kernel(const float* __restrict__ asrc, const float* __restrict__ adst) {
    int gid = blockIdx.x * blockDim.x + threadIdx.x;
    int node = gid >> 5;
    int lane = gid & 31;
    if (node >= NN) return;
    float4 h = *reinterpret_cast<const float4*>(&g_h1[node * HC1 + lane * 4]);
    float4 a = *reinterpret_cast<const float4*>(&asrc[lane * 4]);
    float4 b = *reinterpret_cast<const float4*>(&adst[lane * 4]);
    float ps = h.x * a.x + h.y * a.y + h.z * a.z + h.w * a.w;
    float pd = h.x * b.x + h.y * b.y + h.z * b.z + h.w * b.w;
#pragma unroll
    for (int off = 4; off >= 1; off >>= 1) {
        ps += __shfl_down_sync(0xffffffffu, ps, off);
        pd += __shfl_down_sync(0xffffffffu, pd, off);
    }
    if ((lane & 7) == 0) {
        int head = lane >> 3;
        g_al_src1[node * H1 + head] = ps;
        g_al_dst1[node * H1 + head] = pd;
    }
}

// ---------------- fused agg1: warp per dst node, CSR, no atomics ----------------
// out1[d] = elu( softmax-weighted sum of h1[src] + b1 )
__global__ void agg1_kernel(const float* __restrict__ b1) {
    int gid = blockIdx.x * blockDim.x + threadIdx.x;
    int d = gid >> 5;
    int lane = gid & 31;
    if (d >= NN) return;
    int h = lane >> 3;
    float adh = g_al_dst1[d * H1 + h];
    int j0 = g_off[d], j1 = g_off[d + 1];
    float4 acc = make_float4(0.f, 0.f, 0.f, 0.f);
    float den = 0.f;
    for (int j = j0; j < j1; j++) {
        int s = g_esrc[j];
        float as = g_al_src1[s * H1 + h];
        float w = __expf(leaky(as + adh));
        den += w;
        float4 hv = *reinterpret_cast<const float4*>(&g_h1[s * HC1 + lane * 4]);
        acc.x += w * hv.x; acc.y += w * hv.y;
        acc.z += w * hv.z; acc.w += w * hv.w;
    }
    float inv = 1.f / den;      // self-loop guarantees den > 0
    float4 b = *reinterpret_cast<const float4*>(&b1[lane * 4]);
    float4 o;
    o.x = acc.x * inv + b.x; o.y = acc.y * inv + b.y;
    o.z = acc.z * inv + b.z; o.w = acc.w * inv + b.w;
    o.x = o.x > 0.f ? o.x : expm1f(o.x);
    o.y = o.y > 0.f ? o.y : expm1f(o.y);
    o.z = o.z > 0.f ? o.z : expm1f(o.z);
    o.w = o.w > 0.f ? o.w : expm1f(o.w);
    *reinterpret_cast<float4*>(&g_out1[d * HC1 + lane * 4]) = o;
}

// ---------------- GEMM2: h2[N,32] = out1[N,128] @ W2[128,32] ----------------
#define G2_ROWS 64
__global__ __launch_bounds__(256) void gemm2_kernel(const float* __restrict__ W2) {
    __shared__ float xst[HC1][G2_ROWS];  // 32 KB
    __shared__ float Ws[HC1][OUTC];      // 16 KB
    int tid = threadIdx.x;
    int row0 = blockIdx.x * G2_ROWS;

    const float4* W4 = (const float4*)W2;
    float4* Ws4 = (float4*)Ws;
#pragma unroll
    for (int i = 0; i < 4; i++) Ws4[tid + 256 * i] = W4[tid + 256 * i];
#pragma unroll
    for (int i = 0; i < 8; i++) {
        int idx = tid + 256 * i;          // float4 idx; 32 per row
        int r = idx >> 5, k4 = idx & 31;
        int row = row0 + r;
        float4 v = make_float4(0.f, 0.f, 0.f, 0.f);
        if (row < NN) v = *(const float4*)&g_out1[row * HC1 + k4 * 4];
        xst[k4 * 4 + 0][r] = v.x; xst[k4 * 4 + 1][r] = v.y;
        xst[k4 * 4 + 2][r] = v.z; xst[k4 * 4 + 3][r] = v.w;
    }
    __syncthreads();

    int lane = tid & 31, w = tid >> 5;
    int rb = w * 8;
    float acc[8];
#pragma unroll
    for (int r = 0; r < 8; r++) acc[r] = 0.f;
#pragma unroll
    for (int k = 0; k < HC1; k++) {
        float4 xa = *(float4*)&xst[k][rb];
        float4 xb = *(float4*)&xst[k][rb + 4];
        float wv = Ws[k][lane];
        acc[0] += xa.x * wv; acc[1] += xa.y * wv;
        acc[2] += xa.z * wv; acc[3] += xa.w * wv;
        acc[4] += xb.x * wv; acc[5] += xb.y * wv;
        acc[6] += xb.z * wv; acc[7] += xb.w * wv;
    }
#pragma unroll
    for (int r = 0; r < 8; r++) {
        int row = row0 + rb + r;
        if (row < NN) g_h2[row * OUTC + lane] = acc[r];
    }
}

// ---------------- logits2: 8 lanes per node ----------------
__global__ void logits2_kernel(const float* __restrict__ asrc, const float* __restrict__ adst) {
    int gid = blockIdx.x * blockDim.x + threadIdx.x;
    int node = gid >> 3;
    int sub = gid & 7;
    if (node >= NN) return;
    float4 h = *reinterpret_cast<const float4*>(&g_h2[node * OUTC + sub * 4]);
    float4 a = *reinterpret_cast<const float4*>(&asrc[sub * 4]);
    float4 b = *reinterpret_cast<const float4*>(&adst[sub * 4]);
    float ps = h.x * a.x + h.y * a.y + h.z * a.z + h.w * a.w;
    float pd = h.x * b.x + h.y * b.y + h.z * b.z + h.w * b.w;
#pragma unroll
    for (int off = 4; off >= 1; off >>= 1) {
        ps += __shfl_down_sync(0xffffffffu, ps, off);
        pd += __shfl_down_sync(0xffffffffu, pd, off);
    }
    if (sub == 0) { g_al_src2[node] = ps; g_al_dst2[node] = pd; }
}

// ---------------- fused agg2: warp per dst node ----------------
__global__ void agg2_kernel(float* __restrict__ dout, const float* __restrict__ b2) {
    int gid = blockIdx.x * blockDim.x + threadIdx.x;
    int d = gid >> 5;
    int lane = gid & 31;
    if (d >= NN) return;
    float ad2 = g_al_dst2[d];
    int j0 = g_off[d], j1 = g_off[d + 1];
    float acc = 0.f, den = 0.f;
    for (int j = j0; j < j1; j++) {
        int s = g_esrc[j];
        float as = g_al_src2[s];
        float w = __expf(leaky(as + ad2));
        den += w;
        acc += w * g_h2[s * OUTC + lane];
    }
    dout[d * OUTC + lane] = acc / den + b2[lane];
}

// ---------------- launch ----------------
extern "C" void kernel_launch(void* const* d_in, const int* in_sizes, int n_in,
                              void* d_out, int out_size) {
    const float* x        = (const float*)d_in[0];
    const int*   ei       = (const int*)d_in[1];
    const float* W1       = (const float*)d_in[2];
    const float* att_src1 = (const float*)d_in[3];
    const float* att_dst1 = (const float*)d_in[4];
    const float* b1       = (const float*)d_in[5];
    const float* W2       = (const float*)d_in[6];
    const float* att_src2 = (const float*)d_in[7];
    const float* att_dst2 = (const float*)d_in[8];
    const float* b2       = (const float*)d_in[9];
    float* dout = (float*)d_out;

    const int T = 256;
    detect_kernel<<<1, 32>>>(ei);
    init_kernel<<<(NN + T - 1) / T, T>>>();
    hist_kernel<<<(EETOT + T - 1) / T, T>>>(ei);
    scan1_kernel<<<NB_SCAN, 1024>>>();
    scan2_kernel<<<1, 128>>>();
    scan3_kernel<<<(NN + T - 1) / T, T>>>();
    scatter_kernel<<<(EETOT + T - 1) / T, T>>>(ei);

    gemm1_kernel<<<(NN + G1_ROWS - 1) / G1_ROWS, 256>>>(x, W1);
    logits1_kernel<<<(NN * 32 + T - 1) / T, T>>>(att_src1, att_dst1);
    agg1_kernel<<<(NN * 32 + T - 1) / T, T>>>(b1);

    gemm2_kernel<<<(NN + G2_ROWS - 1) / G2_ROWS, 256>>>(W2);
    logits2_kernel<<<(NN * 8 + T - 1) / T, T>>>(att_src2, att_dst2);
    agg2_kernel<<<(NN * 32 + T - 1) / T, T>>>(dout, b2);
}

// round 3
// speedup vs baseline: 3.7154x; 1.0707x over previous
#include <cuda_runtime.h>
#include <math.h>

// ---------------- problem constants ----------------
#define NN   100000
#define EE0  1600000            // raw edges
#define EETOT (EE0 + NN)        // + self loops
#define C1   64                 // in channels
#define H1   4                  // heads layer1
#define HC1  128                // H1*D1
#define OUTC 32                 // layer2 out channels
#define NB_SCAN 98              // ceil(NN/1024)

// ---------------- scratch (device globals; no allocation) ----------------
__device__ float g_h1[NN * HC1];        // layer1 transformed features
__device__ float g_out1[NN * HC1];      // elu(agg1 + b1)
__device__ float g_al_src1[NN * H1];
__device__ float g_al_dst1[NN * H1];

__device__ float g_h2[NN * OUTC];
__device__ float g_al_src2[NN];
__device__ float g_al_dst2[NN];

// CSR build
__device__ int g_deg[NN];
__device__ int g_cursor[NN];            // init'd to offsets by scan3
__device__ int g_scan[NN];
__device__ int g_bsum[NB_SCAN];
__device__ int g_boff[NB_SCAN];
__device__ int g_off[NN + 1];
__device__ int g_esrc[EETOT];

__device__ int g_is64;

// ---------------- helpers ----------------
__device__ __forceinline__ float leaky(float v) { return v > 0.f ? v : 0.2f * v; }

__device__ __forceinline__ void load_edge(const int* __restrict__ ei, int e, int is64,
                                          int& s, int& d) {
    if (e >= EE0) { s = d = e - EE0; return; }
    if (is64) { s = ei[2 * e]; d = ei[2 * (EE0 + e)]; }
    else      { s = ei[e];     d = ei[EE0 + e]; }
}

// ---------------- CSR build ----------------
__global__ void init_kernel(const int* __restrict__ ei) {
    int i = blockIdx.x * blockDim.x + threadIdx.x;
    if (i < NN) g_deg[i] = 0;
    if (blockIdx.x == 0 && threadIdx.x == 0) {
        int zeros = 0;
        for (int k = 0; k < 256; k++) zeros += (ei[2 * k + 1] == 0);
        g_is64 = (zeros == 256) ? 1 : 0;
    }
}

__global__ void hist_kernel(const int* __restrict__ ei) {
    int e = blockIdx.x * blockDim.x + threadIdx.x;
    if (e >= EETOT) return;
    int is64 = g_is64;
    int d;
    if (e >= EE0) d = e - EE0;
    else d = is64 ? ei[2 * (EE0 + e)] : ei[EE0 + e];
    atomicAdd(&g_deg[d], 1);
}

__global__ void scan1_kernel() {
    __shared__ int warp_tot[32];
    int t = threadIdx.x;
    int i = blockIdx.x * 1024 + t;
    int lane = t & 31, w = t >> 5;
    int v = (i < NN) ? g_deg[i] : 0;
    int sum = v;
#pragma unroll
    for (int o = 1; o < 32; o <<= 1) {
        int u = __shfl_up_sync(0xffffffffu, sum, o);
        if (lane >= o) sum += u;
    }
    if (lane == 31) warp_tot[w] = sum;
    __syncthreads();
    if (w == 0) {
        int s = warp_tot[lane];
#pragma unroll
        for (int o = 1; o < 32; o <<= 1) {
            int u = __shfl_up_sync(0xffffffffu, s, o);
            if (lane >= o) s += u;
        }
        warp_tot[lane] = s;
    }
    __syncthreads();
    int base = (w > 0) ? warp_tot[w - 1] : 0;
    int inc = base + sum;               // inclusive scan
    if (i < NN) g_scan[i] = inc;
    if (t == 1023) g_bsum[blockIdx.x] = inc;
}

__global__ void scan2_kernel() {
    __shared__ int s[128];
    int t = threadIdx.x;
    int v = (t < NB_SCAN) ? g_bsum[t] : 0;
    s[t] = v;
    __syncthreads();
#pragma unroll
    for (int o = 1; o < 128; o <<= 1) {
        int u = (t >= o) ? s[t - o] : 0;
        __syncthreads();
        s[t] += u;
        __syncthreads();
    }
    if (t < NB_SCAN) g_boff[t] = s[t] - v;   // exclusive
}

__global__ void scan3_kernel() {
    int i = blockIdx.x * blockDim.x + threadIdx.x;
    if (i == 0) g_off[0] = 0;
    if (i < NN) {
        int end = g_scan[i] + g_boff[i >> 10];
        g_off[i + 1] = end;
        g_cursor[i] = end - g_deg[i];   // start offset; scatter bumps this
    }
}

__global__ void scatter_kernel(const int* __restrict__ ei) {
    int e = blockIdx.x * blockDim.x + threadIdx.x;
    if (e >= EETOT) return;
    int is64 = g_is64;
    int s, d;
    load_edge(ei, e, is64, s, d);
    int pos = atomicAdd(&g_cursor[d], 1);
    g_esrc[pos] = s;
}

// ---------------- GEMM1 + fused logits1 ----------------
// h1[N,128] = x[N,64] @ W1[64,128]; al_src1/al_dst1[N,4] from epilogue
#define G1_ROWS 64
__global__ __launch_bounds__(256) void gemm1_kernel(const float* __restrict__ x,
                                                    const float* __restrict__ W,
                                                    const float* __restrict__ asrc,
                                                    const float* __restrict__ adst) {
    __shared__ float xst[C1][G1_ROWS];   // [k][row] 16 KB
    __shared__ float Ws[C1][HC1];        // 32 KB
    int tid = threadIdx.x;
    int row0 = blockIdx.x * G1_ROWS;

    const float4* W4 = (const float4*)W;
    float4* Ws4 = (float4*)Ws;
#pragma unroll
    for (int i = 0; i < 8; i++) Ws4[tid + 256 * i] = W4[tid + 256 * i];
#pragma unroll
    for (int i = 0; i < 4; i++) {
        int idx = tid + 256 * i;          // float4 idx; 16 per row
        int r = idx >> 4, k4 = idx & 15;
        int row = row0 + r;
        float4 v = make_float4(0.f, 0.f, 0.f, 0.f);
        if (row < NN) v = *(const float4*)&x[row * C1 + k4 * 4];
        xst[k4 * 4 + 0][r] = v.x; xst[k4 * 4 + 1][r] = v.y;
        xst[k4 * 4 + 2][r] = v.z; xst[k4 * 4 + 3][r] = v.w;
    }
    __syncthreads();

    int lane = tid & 31, w = tid >> 5;
    int rb = w * 8;
    float acc[8][4];
#pragma unroll
    for (int r = 0; r < 8; r++)
#pragma unroll
        for (int c = 0; c < 4; c++) acc[r][c] = 0.f;

#pragma unroll
    for (int k = 0; k < C1; k++) {
        float4 xa = *(float4*)&xst[k][rb];
        float4 xb = *(float4*)&xst[k][rb + 4];
        float4 wv = *(float4*)&Ws[k][lane * 4];
        float xr[8] = {xa.x, xa.y, xa.z, xa.w, xb.x, xb.y, xb.z, xb.w};
#pragma unroll
        for (int r = 0; r < 8; r++) {
            acc[r][0] += xr[r] * wv.x; acc[r][1] += xr[r] * wv.y;
            acc[r][2] += xr[r] * wv.z; acc[r][3] += xr[r] * wv.w;
        }
    }

    float4 av = *(const float4*)&asrc[lane * 4];
    float4 bv = *(const float4*)&adst[lane * 4];
    int head = lane >> 3;
#pragma unroll
    for (int r = 0; r < 8; r++) {
        int row = row0 + rb + r;
        if (row < NN) *(float4*)&g_h1[row * HC1 + lane * 4] = *(float4*)acc[r];
        float ps = acc[r][0] * av.x + acc[r][1] * av.y + acc[r][2] * av.z + acc[r][3] * av.w;
        float pd = acc[r][0] * bv.x + acc[r][1] * bv.y + acc[r][2] * bv.z + acc[r][3] * bv.w;
#pragma unroll
        for (int off = 4; off >= 1; off >>= 1) {
            ps += __shfl_down_sync(0xffffffffu, ps, off);
            pd += __shfl_down_sync(0xffffffffu, pd, off);
        }
        if ((lane & 7) == 0 && row < NN) {
            g_al_src1[row * H1 + head] = ps;
            g_al_dst1[row * H1 + head] = pd;
        }
    }
}

// ---------------- fused agg1: warp per dst node, CSR, no atomics ----------------
__global__ void agg1_kernel(const float* __restrict__ b1) {
    int gid = blockIdx.x * blockDim.x + threadIdx.x;
    int d = gid >> 5;
    int lane = gid & 31;
    if (d >= NN) return;
    int h = lane >> 3;
    const float* __restrict__ als = g_al_src1;
    const int* __restrict__ esrc = g_esrc;
    const float* __restrict__ h1p = g_h1;
    float adh = g_al_dst1[d * H1 + h];
    int j0 = g_off[d], j1 = g_off[d + 1];
    float4 acc = make_float4(0.f, 0.f, 0.f, 0.f);
    float den = 0.f;
    int j = j0;
    for (; j + 1 < j1; j += 2) {
        int s0 = esrc[j], s1 = esrc[j + 1];
        float as0 = als[s0 * H1 + h];
        float as1 = als[s1 * H1 + h];
        float4 hv0 = *reinterpret_cast<const float4*>(&h1p[s0 * HC1 + lane * 4]);
        float4 hv1 = *reinterpret_cast<const float4*>(&h1p[s1 * HC1 + lane * 4]);
        float w0 = __expf(leaky(as0 + adh));
        float w1 = __expf(leaky(as1 + adh));
        den += w0 + w1;
        acc.x += w0 * hv0.x + w1 * hv1.x;
        acc.y += w0 * hv0.y + w1 * hv1.y;
        acc.z += w0 * hv0.z + w1 * hv1.z;
        acc.w += w0 * hv0.w + w1 * hv1.w;
    }
    if (j < j1) {
        int s0 = esrc[j];
        float as0 = als[s0 * H1 + h];
        float4 hv0 = *reinterpret_cast<const float4*>(&h1p[s0 * HC1 + lane * 4]);
        float w0 = __expf(leaky(as0 + adh));
        den += w0;
        acc.x += w0 * hv0.x; acc.y += w0 * hv0.y;
        acc.z += w0 * hv0.z; acc.w += w0 * hv0.w;
    }
    float inv = 1.f / den;      // self-loop guarantees den > 0
    float4 b = *reinterpret_cast<const float4*>(&b1[lane * 4]);
    float4 o;
    o.x = acc.x * inv + b.x; o.y = acc.y * inv + b.y;
    o.z = acc.z * inv + b.z; o.w = acc.w * inv + b.w;
    o.x = o.x > 0.f ? o.x : expm1f(o.x);
    o.y = o.y > 0.f ? o.y : expm1f(o.y);
    o.z = o.z > 0.f ? o.z : expm1f(o.z);
    o.w = o.w > 0.f ? o.w : expm1f(o.w);
    *reinterpret_cast<float4*>(&g_out1[d * HC1 + lane * 4]) = o;
}

// ---------------- GEMM2 + fused logits2 ----------------
#define G2_ROWS 64
__global__ __launch_bounds__(256) void gemm2_kernel(const float* __restrict__ W2,
                                                    const float* __restrict__ asrc,
                                                    const float* __restrict__ adst) {
    __shared__ float xst[HC1][G2_ROWS];  // 32 KB
    __shared__ float Ws[HC1][OUTC];      // 16 KB
    int tid = threadIdx.x;
    int row0 = blockIdx.x * G2_ROWS;

    const float4* W4 = (const float4*)W2;
    float4* Ws4 = (float4*)Ws;
#pragma unroll
    for (int i = 0; i < 4; i++) Ws4[tid + 256 * i] = W4[tid + 256 * i];
#pragma unroll
    for (int i = 0; i < 8; i++) {
        int idx = tid + 256 * i;          // float4 idx; 32 per row
        int r = idx >> 5, k4 = idx & 31;
        int row = row0 + r;
        float4 v = make_float4(0.f, 0.f, 0.f, 0.f);
        if (row < NN) v = *(const float4*)&g_out1[row * HC1 + k4 * 4];
        xst[k4 * 4 + 0][r] = v.x; xst[k4 * 4 + 1][r] = v.y;
        xst[k4 * 4 + 2][r] = v.z; xst[k4 * 4 + 3][r] = v.w;
    }
    __syncthreads();

    int lane = tid & 31, w = tid >> 5;
    int rb = w * 8;
    float acc[8];
#pragma unroll
    for (int r = 0; r < 8; r++) acc[r] = 0.f;
#pragma unroll
    for (int k = 0; k < HC1; k++) {
        float4 xa = *(float4*)&xst[k][rb];
        float4 xb = *(float4*)&xst[k][rb + 4];
        float wv = Ws[k][lane];
        acc[0] += xa.x * wv; acc[1] += xa.y * wv;
        acc[2] += xa.z * wv; acc[3] += xa.w * wv;
        acc[4] += xb.x * wv; acc[5] += xb.y * wv;
        acc[6] += xb.z * wv; acc[7] += xb.w * wv;
    }

    float av = asrc[lane], bv = adst[lane];
#pragma unroll
    for (int r = 0; r < 8; r++) {
        int row = row0 + rb + r;
        if (row < NN) g_h2[row * OUTC + lane] = acc[r];
        float ps = acc[r] * av;
        float pd = acc[r] * bv;
#pragma unroll
        for (int off = 16; off >= 1; off >>= 1) {
            ps += __shfl_down_sync(0xffffffffu, ps, off);
            pd += __shfl_down_sync(0xffffffffu, pd, off);
        }
        if (lane == 0 && row < NN) {
            g_al_src2[row] = ps;
            g_al_dst2[row] = pd;
        }
    }
}

// ---------------- fused agg2: warp per dst node ----------------
__global__ void agg2_kernel(float* __restrict__ dout, const float* __restrict__ b2) {
    int gid = blockIdx.x * blockDim.x + threadIdx.x;
    int d = gid >> 5;
    int lane = gid & 31;
    if (d >= NN) return;
    const float* __restrict__ als = g_al_src2;
    const int* __restrict__ esrc = g_esrc;
    const float* __restrict__ h2p = g_h2;
    float ad2 = g_al_dst2[d];
    int j0 = g_off[d], j1 = g_off[d + 1];
    float acc = 0.f, den = 0.f;
    int j = j0;
    for (; j + 1 < j1; j += 2) {
        int s0 = esrc[j], s1 = esrc[j + 1];
        float as0 = als[s0], as1 = als[s1];
        float v0 = h2p[s0 * OUTC + lane];
        float v1 = h2p[s1 * OUTC + lane];
        float w0 = __expf(leaky(as0 + ad2));
        float w1 = __expf(leaky(as1 + ad2));
        den += w0 + w1;
        acc += w0 * v0 + w1 * v1;
    }
    if (j < j1) {
        int s0 = esrc[j];
        float w0 = __expf(leaky(als[s0] + ad2));
        den += w0;
        acc += w0 * h2p[s0 * OUTC + lane];
    }
    dout[d * OUTC + lane] = acc / den + b2[lane];
}

// ---------------- launch ----------------
extern "C" void kernel_launch(void* const* d_in, const int* in_sizes, int n_in,
                              void* d_out, int out_size) {
    const float* x        = (const float*)d_in[0];
    const int*   ei       = (const int*)d_in[1];
    const float* W1       = (const float*)d_in[2];
    const float* att_src1 = (const float*)d_in[3];
    const float* att_dst1 = (const float*)d_in[4];
    const float* b1       = (const float*)d_in[5];
    const float* W2       = (const float*)d_in[6];
    const float* att_src2 = (const float*)d_in[7];
    const float* att_dst2 = (const float*)d_in[8];
    const float* b2       = (const float*)d_in[9];
    float* dout = (float*)d_out;

    const int T = 256;
    init_kernel<<<(NN + T - 1) / T, T>>>(ei);
    hist_kernel<<<(EETOT + T - 1) / T, T>>>(ei);
    scan1_kernel<<<NB_SCAN, 1024>>>();
    scan2_kernel<<<1, 128>>>();
    scan3_kernel<<<(NN + T - 1) / T, T>>>();
    scatter_kernel<<<(EETOT + T - 1) / T, T>>>(ei);

    gemm1_kernel<<<(NN + G1_ROWS - 1) / G1_ROWS, 256>>>(x, W1, att_src1, att_dst1);
    agg1_kernel<<<(NN * 32 + T - 1) / T, T>>>(b1);

    gemm2_kernel<<<(NN + G2_ROWS - 1) / G2_ROWS, 256>>>(W2, att_src2, att_dst2);
    agg2_kernel<<<(NN * 32 + T - 1) / T, T>>>(dout, b2);
}

// round 4
// speedup vs baseline: 3.9930x; 1.0747x over previous
#include <cuda_runtime.h>
#include <cuda_fp16.h>
#include <math.h>

// ---------------- problem constants ----------------
#define NN   100000
#define EE0  1600000            // raw edges
#define EETOT (EE0 + NN)        // + self loops
#define C1   64                 // in channels
#define H1   4                  // heads layer1
#define HC1  128                // H1*D1
#define OUTC 32                 // layer2 out channels
#define NB_SCAN 98              // ceil(NN/1024)

// ---------------- scratch (device globals; no allocation) ----------------
__device__ __half g_h1h[NN * HC1];      // layer1 features (fp16, gather-only)
__device__ __half g_out1h[NN * HC1];    // elu(agg1 + b1) (fp16, gemm2 input)
__device__ float  g_al_src1[NN * H1];
__device__ float  g_al_dst1[NN * H1];

__device__ __half g_h2h[NN * OUTC];     // layer2 features (fp16, gather-only)
__device__ float  g_al_src2[NN];
__device__ float  g_al_dst2[NN];

// CSR build
__device__ int g_deg[NN];
__device__ int g_cursor[NN];            // init'd to start offsets by scan3
__device__ int g_scan[NN];
__device__ int g_bsum[NB_SCAN];
__device__ int g_boff[NB_SCAN];
__device__ int g_off[NN + 1];
__device__ int g_esrc[EETOT];

__device__ int g_is64;

// ---------------- helpers ----------------
__device__ __forceinline__ float leaky(float v) { return v > 0.f ? v : 0.2f * v; }

__device__ __forceinline__ void load_edge(const int* __restrict__ ei, int e, int is64,
                                          int& s, int& d) {
    if (e >= EE0) { s = d = e - EE0; return; }
    if (is64) { s = ei[2 * e]; d = ei[2 * (EE0 + e)]; }
    else      { s = ei[e];     d = ei[EE0 + e]; }
}

// ---------------- CSR build ----------------
__global__ void init_kernel(const int* __restrict__ ei) {
    int i = blockIdx.x * blockDim.x + threadIdx.x;
    if (i < NN) g_deg[i] = 0;
    if (blockIdx.x == 0 && threadIdx.x == 0) {
        int zeros = 0;
        for (int k = 0; k < 256; k++) zeros += (ei[2 * k + 1] == 0);
        g_is64 = (zeros == 256) ? 1 : 0;
    }
}

__global__ void hist_kernel(const int* __restrict__ ei) {
    int e = blockIdx.x * blockDim.x + threadIdx.x;
    if (e >= EETOT) return;
    int is64 = g_is64;
    int d;
    if (e >= EE0) d = e - EE0;
    else d = is64 ? ei[2 * (EE0 + e)] : ei[EE0 + e];
    atomicAdd(&g_deg[d], 1);
}

__global__ void scan1_kernel() {
    __shared__ int warp_tot[32];
    int t = threadIdx.x;
    int i = blockIdx.x * 1024 + t;
    int lane = t & 31, w = t >> 5;
    int v = (i < NN) ? g_deg[i] : 0;
    int sum = v;
#pragma unroll
    for (int o = 1; o < 32; o <<= 1) {
        int u = __shfl_up_sync(0xffffffffu, sum, o);
        if (lane >= o) sum += u;
    }
    if (lane == 31) warp_tot[w] = sum;
    __syncthreads();
    if (w == 0) {
        int s = warp_tot[lane];
#pragma unroll
        for (int o = 1; o < 32; o <<= 1) {
            int u = __shfl_up_sync(0xffffffffu, s, o);
            if (lane >= o) s += u;
        }
        warp_tot[lane] = s;
    }
    __syncthreads();
    int base = (w > 0) ? warp_tot[w - 1] : 0;
    int inc = base + sum;               // inclusive scan
    if (i < NN) g_scan[i] = inc;
    if (t == 1023) g_bsum[blockIdx.x] = inc;
}

__global__ void scan2_kernel() {
    __shared__ int s[128];
    int t = threadIdx.x;
    int v = (t < NB_SCAN) ? g_bsum[t] : 0;
    s[t] = v;
    __syncthreads();
#pragma unroll
    for (int o = 1; o < 128; o <<= 1) {
        int u = (t >= o) ? s[t - o] : 0;
        __syncthreads();
        s[t] += u;
        __syncthreads();
    }
    if (t < NB_SCAN) g_boff[t] = s[t] - v;   // exclusive
}

__global__ void scan3_kernel() {
    int i = blockIdx.x * blockDim.x + threadIdx.x;
    if (i == 0) g_off[0] = 0;
    if (i < NN) {
        int end = g_scan[i] + g_boff[i >> 10];
        g_off[i + 1] = end;
        g_cursor[i] = end - g_deg[i];   // start offset; scatter bumps this
    }
}

__global__ void scatter_kernel(const int* __restrict__ ei) {
    int e = blockIdx.x * blockDim.x + threadIdx.x;
    if (e >= EETOT) return;
    int is64 = g_is64;
    int s, d;
    load_edge(ei, e, is64, s, d);
    int pos = atomicAdd(&g_cursor[d], 1);
    g_esrc[pos] = s;
}

// ---------------- GEMM1 + fused logits1 ----------------
// h1[N,128] = x[N,64] @ W1[64,128]; al_src1/al_dst1[N,4] from epilogue
#define G1_ROWS 64
__global__ __launch_bounds__(256) void gemm1_kernel(const float* __restrict__ x,
                                                    const float* __restrict__ W,
                                                    const float* __restrict__ asrc,
                                                    const float* __restrict__ adst) {
    __shared__ float xst[C1][G1_ROWS];   // [k][row] 16 KB
    __shared__ float Ws[C1][HC1];        // 32 KB
    int tid = threadIdx.x;
    int row0 = blockIdx.x * G1_ROWS;

    const float4* W4 = (const float4*)W;
    float4* Ws4 = (float4*)Ws;
#pragma unroll
    for (int i = 0; i < 8; i++) Ws4[tid + 256 * i] = W4[tid + 256 * i];
#pragma unroll
    for (int i = 0; i < 4; i++) {
        int idx = tid + 256 * i;          // float4 idx; 16 per row
        int r = idx >> 4, k4 = idx & 15;
        int row = row0 + r;
        float4 v = make_float4(0.f, 0.f, 0.f, 0.f);
        if (row < NN) v = *(const float4*)&x[row * C1 + k4 * 4];
        xst[k4 * 4 + 0][r] = v.x; xst[k4 * 4 + 1][r] = v.y;
        xst[k4 * 4 + 2][r] = v.z; xst[k4 * 4 + 3][r] = v.w;
    }
    __syncthreads();

    int lane = tid & 31, w = tid >> 5;
    int rb = w * 8;
    float acc[8][4];
#pragma unroll
    for (int r = 0; r < 8; r++)
#pragma unroll
        for (int c = 0; c < 4; c++) acc[r][c] = 0.f;

#pragma unroll
    for (int k = 0; k < C1; k++) {
        float4 xa = *(float4*)&xst[k][rb];
        float4 xb = *(float4*)&xst[k][rb + 4];
        float4 wv = *(float4*)&Ws[k][lane * 4];
        float xr[8] = {xa.x, xa.y, xa.z, xa.w, xb.x, xb.y, xb.z, xb.w};
#pragma unroll
        for (int r = 0; r < 8; r++) {
            acc[r][0] += xr[r] * wv.x; acc[r][1] += xr[r] * wv.y;
            acc[r][2] += xr[r] * wv.z; acc[r][3] += xr[r] * wv.w;
        }
    }

    float4 av = *(const float4*)&asrc[lane * 4];
    float4 bv = *(const float4*)&adst[lane * 4];
    int head = lane >> 3;
#pragma unroll
    for (int r = 0; r < 8; r++) {
        int row = row0 + rb + r;
        if (row < NN) {
            __half2 p0 = __floats2half2_rn(acc[r][0], acc[r][1]);
            __half2 p1 = __floats2half2_rn(acc[r][2], acc[r][3]);
            uint2 u;
            u.x = *reinterpret_cast<unsigned*>(&p0);
            u.y = *reinterpret_cast<unsigned*>(&p1);
            *reinterpret_cast<uint2*>(&g_h1h[row * HC1 + lane * 4]) = u;
        }
        float ps = acc[r][0] * av.x + acc[r][1] * av.y + acc[r][2] * av.z + acc[r][3] * av.w;
        float pd = acc[r][0] * bv.x + acc[r][1] * bv.y + acc[r][2] * bv.z + acc[r][3] * bv.w;
#pragma unroll
        for (int off = 4; off >= 1; off >>= 1) {
            ps += __shfl_down_sync(0xffffffffu, ps, off);
            pd += __shfl_down_sync(0xffffffffu, pd, off);
        }
        if ((lane & 7) == 0 && row < NN) {
            g_al_src1[row * H1 + head] = ps;
            g_al_dst1[row * H1 + head] = pd;
        }
    }
}

// ---------------- fused agg1: warp per dst node, CSR, no atomics ----------------
__device__ __forceinline__ void h4load(const __half* p, float& f0, float& f1,
                                       float& f2, float& f3) {
    uint2 u = *reinterpret_cast<const uint2*>(p);
    __half2 a = *reinterpret_cast<__half2*>(&u.x);
    __half2 b = *reinterpret_cast<__half2*>(&u.y);
    float2 fa = __half22float2(a), fb = __half22float2(b);
    f0 = fa.x; f1 = fa.y; f2 = fb.x; f3 = fb.y;
}

__global__ void agg1_kernel(const float* __restrict__ b1) {
    int gid = blockIdx.x * blockDim.x + threadIdx.x;
    int d = gid >> 5;
    int lane = gid & 31;
    if (d >= NN) return;
    int h = lane >> 3;
    const float* __restrict__ als = g_al_src1;
    const int* __restrict__ esrc = g_esrc;
    const __half* __restrict__ h1p = g_h1h;
    float adh = g_al_dst1[d * H1 + h];
    int j0 = g_off[d], j1 = g_off[d + 1];
    float4 acc = make_float4(0.f, 0.f, 0.f, 0.f);
    float den = 0.f;
    int j = j0;
    for (; j + 1 < j1; j += 2) {
        int s0 = esrc[j], s1 = esrc[j + 1];
        float as0 = als[s0 * H1 + h];
        float as1 = als[s1 * H1 + h];
        float a0, a1, a2, a3, c0, c1, c2, c3;
        h4load(&h1p[s0 * HC1 + lane * 4], a0, a1, a2, a3);
        h4load(&h1p[s1 * HC1 + lane * 4], c0, c1, c2, c3);
        float w0 = __expf(leaky(as0 + adh));
        float w1 = __expf(leaky(as1 + adh));
        den += w0 + w1;
        acc.x += w0 * a0 + w1 * c0;
        acc.y += w0 * a1 + w1 * c1;
        acc.z += w0 * a2 + w1 * c2;
        acc.w += w0 * a3 + w1 * c3;
    }
    if (j < j1) {
        int s0 = esrc[j];
        float as0 = als[s0 * H1 + h];
        float a0, a1, a2, a3;
        h4load(&h1p[s0 * HC1 + lane * 4], a0, a1, a2, a3);
        float w0 = __expf(leaky(as0 + adh));
        den += w0;
        acc.x += w0 * a0; acc.y += w0 * a1;
        acc.z += w0 * a2; acc.w += w0 * a3;
    }
    float inv = 1.f / den;      // self-loop guarantees den > 0
    float4 b = *reinterpret_cast<const float4*>(&b1[lane * 4]);
    float4 o;
    o.x = acc.x * inv + b.x; o.y = acc.y * inv + b.y;
    o.z = acc.z * inv + b.z; o.w = acc.w * inv + b.w;
    o.x = o.x > 0.f ? o.x : expm1f(o.x);
    o.y = o.y > 0.f ? o.y : expm1f(o.y);
    o.z = o.z > 0.f ? o.z : expm1f(o.z);
    o.w = o.w > 0.f ? o.w : expm1f(o.w);
    __half2 p0 = __floats2half2_rn(o.x, o.y);
    __half2 p1 = __floats2half2_rn(o.z, o.w);
    uint2 u;
    u.x = *reinterpret_cast<unsigned*>(&p0);
    u.y = *reinterpret_cast<unsigned*>(&p1);
    *reinterpret_cast<uint2*>(&g_out1h[d * HC1 + lane * 4]) = u;
}

// ---------------- GEMM2 + fused logits2 ----------------
// h2[N,32] = out1[N,128] @ W2[128,32]
#define G2_ROWS 64
__global__ __launch_bounds__(256) void gemm2_kernel(const float* __restrict__ W2,
                                                    const float* __restrict__ asrc,
                                                    const float* __restrict__ adst) {
    __shared__ float xst[HC1][G2_ROWS];  // 32 KB
    __shared__ float Ws[HC1][OUTC];      // 16 KB
    int tid = threadIdx.x;
    int row0 = blockIdx.x * G2_ROWS;

    const float4* W4 = (const float4*)W2;
    float4* Ws4 = (float4*)Ws;
#pragma unroll
    for (int i = 0; i < 4; i++) Ws4[tid + 256 * i] = W4[tid + 256 * i];
#pragma unroll
    for (int i = 0; i < 4; i++) {
        int idx = tid + 256 * i;          // uint4 (8 halves) idx; 16 per row
        int r = idx >> 4, k8 = idx & 15;
        int row = row0 + r;
        uint4 v = make_uint4(0u, 0u, 0u, 0u);
        if (row < NN) v = *(const uint4*)&g_out1h[row * HC1 + k8 * 8];
        const unsigned uu[4] = {v.x, v.y, v.z, v.w};
#pragma unroll
        for (int q = 0; q < 4; q++) {
            __half2 hh = *reinterpret_cast<const __half2*>(&uu[q]);
            float2 ff = __half22float2(hh);
            xst[k8 * 8 + q * 2 + 0][r] = ff.x;
            xst[k8 * 8 + q * 2 + 1][r] = ff.y;
        }
    }
    __syncthreads();

    int lane = tid & 31, w = tid >> 5;
    int rb = w * 8;
    float acc[8];
#pragma unroll
    for (int r = 0; r < 8; r++) acc[r] = 0.f;
#pragma unroll
    for (int k = 0; k < HC1; k++) {
        float4 xa = *(float4*)&xst[k][rb];
        float4 xb = *(float4*)&xst[k][rb + 4];
        float wv = Ws[k][lane];
        acc[0] += xa.x * wv; acc[1] += xa.y * wv;
        acc[2] += xa.z * wv; acc[3] += xa.w * wv;
        acc[4] += xb.x * wv; acc[5] += xb.y * wv;
        acc[6] += xb.z * wv; acc[7] += xb.w * wv;
    }

    float av = asrc[lane], bv = adst[lane];
#pragma unroll
    for (int r = 0; r < 8; r++) {
        int row = row0 + rb + r;
        if (row < NN) g_h2h[row * OUTC + lane] = __float2half_rn(acc[r]);
        float ps = acc[r] * av;
        float pd = acc[r] * bv;
#pragma unroll
        for (int off = 16; off >= 1; off >>= 1) {
            ps += __shfl_down_sync(0xffffffffu, ps, off);
            pd += __shfl_down_sync(0xffffffffu, pd, off);
        }
        if (lane == 0 && row < NN) {
            g_al_src2[row] = ps;
            g_al_dst2[row] = pd;
        }
    }
}

// ---------------- fused agg2: warp per dst node ----------------
__global__ void agg2_kernel(float* __restrict__ dout, const float* __restrict__ b2) {
    int gid = blockIdx.x * blockDim.x + threadIdx.x;
    int d = gid >> 5;
    int lane = gid & 31;
    if (d >= NN) return;
    const float* __restrict__ als = g_al_src2;
    const int* __restrict__ esrc = g_esrc;
    const __half* __restrict__ h2p = g_h2h;
    float ad2 = g_al_dst2[d];
    int j0 = g_off[d], j1 = g_off[d + 1];
    float acc = 0.f, den = 0.f;
    int j = j0;
    for (; j + 1 < j1; j += 2) {
        int s0 = esrc[j], s1 = esrc[j + 1];
        float as0 = als[s0], as1 = als[s1];
        float v0 = __half2float(h2p[s0 * OUTC + lane]);
        float v1 = __half2float(h2p[s1 * OUTC + lane]);
        float w0 = __expf(leaky(as0 + ad2));
        float w1 = __expf(leaky(as1 + ad2));
        den += w0 + w1;
        acc += w0 * v0 + w1 * v1;
    }
    if (j < j1) {
        int s0 = esrc[j];
        float w0 = __expf(leaky(als[s0] + ad2));
        den += w0;
        acc += w0 * __half2float(h2p[s0 * OUTC + lane]);
    }
    dout[d * OUTC + lane] = acc / den + b2[lane];
}

// ---------------- launch ----------------
extern "C" void kernel_launch(void* const* d_in, const int* in_sizes, int n_in,
                              void* d_out, int out_size) {
    const float* x        = (const float*)d_in[0];
    const int*   ei       = (const int*)d_in[1];
    const float* W1       = (const float*)d_in[2];
    const float* att_src1 = (const float*)d_in[3];
    const float* att_dst1 = (const float*)d_in[4];
    const float* b1       = (const float*)d_in[5];
    const float* W2       = (const float*)d_in[6];
    const float* att_src2 = (const float*)d_in[7];
    const float* att_dst2 = (const float*)d_in[8];
    const float* b2       = (const float*)d_in[9];
    float* dout = (float*)d_out;

    const int T = 256;
    init_kernel<<<(NN + T - 1) / T, T>>>(ei);
    hist_kernel<<<(EETOT + T - 1) / T, T>>>(ei);
    scan1_kernel<<<NB_SCAN, 1024>>>();
    scan2_kernel<<<1, 128>>>();
    scan3_kernel<<<(NN + T - 1) / T, T>>>();
    scatter_kernel<<<(EETOT + T - 1) / T, T>>>(ei);

    gemm1_kernel<<<(NN + G1_ROWS - 1) / G1_ROWS, 256>>>(x, W1, att_src1, att_dst1);
    agg1_kernel<<<(NN * 32 + T - 1) / T, T>>>(b1);

    gemm2_kernel<<<(NN + G2_ROWS - 1) / G2_ROWS, 256>>>(W2, att_src2, att_dst2);
    agg2_kernel<<<(NN * 32 + T - 1) / T, T>>>(dout, b2);
}

// round 5
// speedup vs baseline: 4.0544x; 1.0154x over previous
#include <cuda_runtime.h>
#include <cuda_fp16.h>
#include <math.h>

// ---------------- problem constants ----------------
#define NN   100000
#define EE0  1600000            // raw edges
#define EETOT (EE0 + NN)        // + self loops
#define C1   64                 // in channels
#define H1   4                  // heads layer1
#define HC1  128                // H1*D1
#define OUTC 32                 // layer2 out channels
#define NB_SCAN 98              // ceil(NN/1024)

typedef unsigned long long u64;
#define FMA_X2(d, a, b, c) \
    asm("fma.rn.f32x2 %0, %1, %2, %3;" : "=l"(d) : "l"(a), "l"(b), "l"(c))
#define PACK2(d, lo, hi) \
    asm("mov.b64 %0, {%1, %2};" : "=l"(d) : "f"(lo), "f"(hi))
#define UNPACK2(lo, hi, s) \
    asm("mov.b64 {%0, %1}, %2;" : "=f"(lo), "=f"(hi) : "l"(s))

union F4U2 { float4 f4; u64 u[2]; };

// ---------------- scratch (device globals; no allocation) ----------------
__device__ __half g_h1h[NN * HC1];      // layer1 features (fp16, gather-only)
__device__ __half g_out1h[NN * HC1];    // elu(agg1 + b1) (fp16, gemm2 input)
__device__ float  g_al_src1[NN * H1];
__device__ float  g_al_dst1[NN * H1];

__device__ __half g_h2h[NN * OUTC];     // layer2 features (fp16, gather-only)
__device__ float  g_al_src2[NN];
__device__ float  g_al_dst2[NN];

// CSR build
__device__ int g_deg[NN];
__device__ int g_cursor[NN];            // init'd to start offsets by scan3
__device__ int g_scan[NN];
__device__ int g_bsum[NB_SCAN];
__device__ int g_boff[NB_SCAN];
__device__ int g_off[NN + 1];
__device__ int g_esrc[EETOT];

__device__ int g_is64;

// ---------------- helpers ----------------
__device__ __forceinline__ float leaky(float v) { return v > 0.f ? v : 0.2f * v; }

__device__ __forceinline__ void load_edge(const int* __restrict__ ei, int e, int is64,
                                          int& s, int& d) {
    if (e >= EE0) { s = d = e - EE0; return; }
    if (is64) { s = ei[2 * e]; d = ei[2 * (EE0 + e)]; }
    else      { s = ei[e];     d = ei[EE0 + e]; }
}

__device__ __forceinline__ void h4load(const __half* p, float& f0, float& f1,
                                       float& f2, float& f3) {
    uint2 u = *reinterpret_cast<const uint2*>(p);
    __half2 a = *reinterpret_cast<__half2*>(&u.x);
    __half2 b = *reinterpret_cast<__half2*>(&u.y);
    float2 fa = __half22float2(a), fb = __half22float2(b);
    f0 = fa.x; f1 = fa.y; f2 = fb.x; f3 = fb.y;
}

// ---------------- CSR build ----------------
__global__ void init_kernel(const int* __restrict__ ei) {
    int i = blockIdx.x * blockDim.x + threadIdx.x;
    if (i < NN) g_deg[i] = 0;
    if (blockIdx.x == 0 && threadIdx.x == 0) {
        int zeros = 0;
        for (int k = 0; k < 256; k++) zeros += (ei[2 * k + 1] == 0);
        g_is64 = (zeros == 256) ? 1 : 0;
    }
}

__global__ void hist_kernel(const int* __restrict__ ei) {
    int e = blockIdx.x * blockDim.x + threadIdx.x;
    if (e >= EETOT) return;
    int is64 = g_is64;
    int d;
    if (e >= EE0) d = e - EE0;
    else d = is64 ? ei[2 * (EE0 + e)] : ei[EE0 + e];
    atomicAdd(&g_deg[d], 1);
}

__global__ void scan1_kernel() {
    __shared__ int warp_tot[32];
    int t = threadIdx.x;
    int i = blockIdx.x * 1024 + t;
    int lane = t & 31, w = t >> 5;
    int v = (i < NN) ? g_deg[i] : 0;
    int sum = v;
#pragma unroll
    for (int o = 1; o < 32; o <<= 1) {
        int u = __shfl_up_sync(0xffffffffu, sum, o);
        if (lane >= o) sum += u;
    }
    if (lane == 31) warp_tot[w] = sum;
    __syncthreads();
    if (w == 0) {
        int s = warp_tot[lane];
#pragma unroll
        for (int o = 1; o < 32; o <<= 1) {
            int u = __shfl_up_sync(0xffffffffu, s, o);
            if (lane >= o) s += u;
        }
        warp_tot[lane] = s;
    }
    __syncthreads();
    int base = (w > 0) ? warp_tot[w - 1] : 0;
    int inc = base + sum;               // inclusive scan
    if (i < NN) g_scan[i] = inc;
    if (t == 1023) g_bsum[blockIdx.x] = inc;
}

__global__ void scan2_kernel() {
    __shared__ int warp_tot[4];
    int t = threadIdx.x;                // 128
    int lane = t & 31, w = t >> 5;
    int v = (t < NB_SCAN) ? g_bsum[t] : 0;
    int sum = v;
#pragma unroll
    for (int o = 1; o < 32; o <<= 1) {
        int u = __shfl_up_sync(0xffffffffu, sum, o);
        if (lane >= o) sum += u;
    }
    if (lane == 31) warp_tot[w] = sum;
    __syncthreads();
    int base = 0;
#pragma unroll
    for (int q = 0; q < 4; q++) base += (q < w) ? warp_tot[q] : 0;
    if (t < NB_SCAN) g_boff[t] = base + sum - v;   // exclusive
}

__global__ void scan3_kernel() {
    int i = blockIdx.x * blockDim.x + threadIdx.x;
    if (i == 0) g_off[0] = 0;
    if (i < NN) {
        int end = g_scan[i] + g_boff[i >> 10];
        g_off[i + 1] = end;
        g_cursor[i] = end - g_deg[i];   // start offset; scatter bumps this
    }
}

__global__ void scatter_kernel(const int* __restrict__ ei) {
    int e = blockIdx.x * blockDim.x + threadIdx.x;
    if (e >= EETOT) return;
    int is64 = g_is64;
    int s, d;
    load_edge(ei, e, is64, s, d);
    int pos = atomicAdd(&g_cursor[d], 1);
    g_esrc[pos] = s;
}

// ---------------- GEMM1 + fused logits1 ----------------
// h1[N,128] = x[N,64] @ W1[64,128]; al_src1/al_dst1[N,4] from epilogue
#define G1_ROWS 64
__global__ __launch_bounds__(256) void gemm1_kernel(const float* __restrict__ x,
                                                    const float* __restrict__ W,
                                                    const float* __restrict__ asrc,
                                                    const float* __restrict__ adst) {
    __shared__ float xst[C1][G1_ROWS];   // [k][row] 16 KB
    __shared__ float Ws[C1][HC1];        // 32 KB
    int tid = threadIdx.x;
    int row0 = blockIdx.x * G1_ROWS;

    const float4* W4 = (const float4*)W;
    float4* Ws4 = (float4*)Ws;
#pragma unroll
    for (int i = 0; i < 8; i++) Ws4[tid + 256 * i] = W4[tid + 256 * i];
#pragma unroll
    for (int i = 0; i < 4; i++) {
        int idx = tid + 256 * i;          // float4 idx; 16 per row
        int r = idx >> 4, k4 = idx & 15;
        int row = row0 + r;
        float4 v = make_float4(0.f, 0.f, 0.f, 0.f);
        if (row < NN) v = *(const float4*)&x[row * C1 + k4 * 4];
        xst[k4 * 4 + 0][r] = v.x; xst[k4 * 4 + 1][r] = v.y;
        xst[k4 * 4 + 2][r] = v.z; xst[k4 * 4 + 3][r] = v.w;
    }
    __syncthreads();

    int lane = tid & 31, w = tid >> 5;
    int rb = w * 8;
    u64 acc2[4][4];                     // [row-pair][col]
#pragma unroll
    for (int m = 0; m < 4; m++)
#pragma unroll
        for (int c = 0; c < 4; c++) acc2[m][c] = 0ull;

#pragma unroll
    for (int k = 0; k < C1; k++) {
        F4U2 xa, xb;
        xa.f4 = *(float4*)&xst[k][rb];
        xb.f4 = *(float4*)&xst[k][rb + 4];
        float4 wv = *(float4*)&Ws[k][lane * 4];
        u64 wd[4];
        PACK2(wd[0], wv.x, wv.x); PACK2(wd[1], wv.y, wv.y);
        PACK2(wd[2], wv.z, wv.z); PACK2(wd[3], wv.w, wv.w);
        u64 xp[4] = {xa.u[0], xa.u[1], xb.u[0], xb.u[1]};
#pragma unroll
        for (int m = 0; m < 4; m++) {
            FMA_X2(acc2[m][0], xp[m], wd[0], acc2[m][0]);
            FMA_X2(acc2[m][1], xp[m], wd[1], acc2[m][1]);
            FMA_X2(acc2[m][2], xp[m], wd[2], acc2[m][2]);
            FMA_X2(acc2[m][3], xp[m], wd[3], acc2[m][3]);
        }
    }

    float acc[8][4];
#pragma unroll
    for (int m = 0; m < 4; m++)
#pragma unroll
        for (int c = 0; c < 4; c++)
            UNPACK2(acc[2 * m][c], acc[2 * m + 1][c], acc2[m][c]);

    float4 av = *(const float4*)&asrc[lane * 4];
    float4 bv = *(const float4*)&adst[lane * 4];
    int head = lane >> 3;
#pragma unroll
    for (int r = 0; r < 8; r++) {
        int row = row0 + rb + r;
        if (row < NN) {
            __half2 p0 = __floats2half2_rn(acc[r][0], acc[r][1]);
            __half2 p1 = __floats2half2_rn(acc[r][2], acc[r][3]);
            uint2 u;
            u.x = *reinterpret_cast<unsigned*>(&p0);
            u.y = *reinterpret_cast<unsigned*>(&p1);
            *reinterpret_cast<uint2*>(&g_h1h[row * HC1 + lane * 4]) = u;
        }
        float ps = acc[r][0] * av.x + acc[r][1] * av.y + acc[r][2] * av.z + acc[r][3] * av.w;
        float pd = acc[r][0] * bv.x + acc[r][1] * bv.y + acc[r][2] * bv.z + acc[r][3] * bv.w;
#pragma unroll
        for (int off = 4; off >= 1; off >>= 1) {
            ps += __shfl_down_sync(0xffffffffu, ps, off);
            pd += __shfl_down_sync(0xffffffffu, pd, off);
        }
        if ((lane & 7) == 0 && row < NN) {
            g_al_src1[row * H1 + head] = ps;
            g_al_dst1[row * H1 + head] = pd;
        }
    }
}

// ---------------- fused agg1: warp per dst node, CSR, no atomics ----------------
__global__ void agg1_kernel(const float* __restrict__ b1) {
    int gid = blockIdx.x * blockDim.x + threadIdx.x;
    int d = gid >> 5;
    int lane = gid & 31;
    if (d >= NN) return;
    int h = lane >> 3;
    const float* __restrict__ als = g_al_src1;
    const int* __restrict__ esrc = g_esrc;
    const __half* __restrict__ h1p = g_h1h;
    float adh = g_al_dst1[d * H1 + h];
    int j0 = g_off[d], j1 = g_off[d + 1];
    float4 acc = make_float4(0.f, 0.f, 0.f, 0.f);
    float den = 0.f;
    int j = j0;
    for (; j + 3 < j1; j += 4) {
        int s0 = esrc[j],     s1 = esrc[j + 1];
        int s2 = esrc[j + 2], s3 = esrc[j + 3];
        float as0 = als[s0 * H1 + h];
        float as1 = als[s1 * H1 + h];
        float as2 = als[s2 * H1 + h];
        float as3 = als[s3 * H1 + h];
        float a0, a1, a2, a3, c0, c1, c2, c3;
        float e0, e1, e2, e3, f0, f1, f2, f3;
        h4load(&h1p[s0 * HC1 + lane * 4], a0, a1, a2, a3);
        h4load(&h1p[s1 * HC1 + lane * 4], c0, c1, c2, c3);
        h4load(&h1p[s2 * HC1 + lane * 4], e0, e1, e2, e3);
        h4load(&h1p[s3 * HC1 + lane * 4], f0, f1, f2, f3);
        float w0 = __expf(leaky(as0 + adh));
        float w1 = __expf(leaky(as1 + adh));
        float w2 = __expf(leaky(as2 + adh));
        float w3 = __expf(leaky(as3 + adh));
        den += (w0 + w1) + (w2 + w3);
        acc.x += w0 * a0 + w1 * c0 + w2 * e0 + w3 * f0;
        acc.y += w0 * a1 + w1 * c1 + w2 * e1 + w3 * f1;
        acc.z += w0 * a2 + w1 * c2 + w2 * e2 + w3 * f2;
        acc.w += w0 * a3 + w1 * c3 + w2 * e3 + w3 * f3;
    }
    for (; j < j1; j++) {
        int s0 = esrc[j];
        float as0 = als[s0 * H1 + h];
        float a0, a1, a2, a3;
        h4load(&h1p[s0 * HC1 + lane * 4], a0, a1, a2, a3);
        float w0 = __expf(leaky(as0 + adh));
        den += w0;
        acc.x += w0 * a0; acc.y += w0 * a1;
        acc.z += w0 * a2; acc.w += w0 * a3;
    }
    float inv = 1.f / den;      // self-loop guarantees den > 0
    float4 b = *reinterpret_cast<const float4*>(&b1[lane * 4]);
    float4 o;
    o.x = acc.x * inv + b.x; o.y = acc.y * inv + b.y;
    o.z = acc.z * inv + b.z; o.w = acc.w * inv + b.w;
    o.x = o.x > 0.f ? o.x : expm1f(o.x);
    o.y = o.y > 0.f ? o.y : expm1f(o.y);
    o.z = o.z > 0.f ? o.z : expm1f(o.z);
    o.w = o.w > 0.f ? o.w : expm1f(o.w);
    __half2 p0 = __floats2half2_rn(o.x, o.y);
    __half2 p1 = __floats2half2_rn(o.z, o.w);
    uint2 u;
    u.x = *reinterpret_cast<unsigned*>(&p0);
    u.y = *reinterpret_cast<unsigned*>(&p1);
    *reinterpret_cast<uint2*>(&g_out1h[d * HC1 + lane * 4]) = u;
}

// ---------------- GEMM2 + fused logits2 ----------------
// h2[N,32] = out1[N,128] @ W2[128,32]
#define G2_ROWS 64
__global__ __launch_bounds__(256) void gemm2_kernel(const float* __restrict__ W2,
                                                    const float* __restrict__ asrc,
                                                    const float* __restrict__ adst) {
    __shared__ float xst[HC1][G2_ROWS];  // 32 KB
    __shared__ float Ws[HC1][OUTC];      // 16 KB
    int tid = threadIdx.x;
    int row0 = blockIdx.x * G2_ROWS;

    const float4* W4 = (const float4*)W2;
    float4* Ws4 = (float4*)Ws;
#pragma unroll
    for (int i = 0; i < 4; i++) Ws4[tid + 256 * i] = W4[tid + 256 * i];
#pragma unroll
    for (int i = 0; i < 4; i++) {
        int idx = tid + 256 * i;          // uint4 (8 halves) idx; 16 per row
        int r = idx >> 4, k8 = idx & 15;
        int row = row0 + r;
        uint4 v = make_uint4(0u, 0u, 0u, 0u);
        if (row < NN) v = *(const uint4*)&g_out1h[row * HC1 + k8 * 8];
        const unsigned uu[4] = {v.x, v.y, v.z, v.w};
#pragma unroll
        for (int q = 0; q < 4; q++) {
            __half2 hh = *reinterpret_cast<const __half2*>(&uu[q]);
            float2 ff = __half22float2(hh);
            xst[k8 * 8 + q * 2 + 0][r] = ff.x;
            xst[k8 * 8 + q * 2 + 1][r] = ff.y;
        }
    }
    __syncthreads();

    int lane = tid & 31, w = tid >> 5;
    int rb = w * 8;
    u64 acc2[4];
#pragma unroll
    for (int m = 0; m < 4; m++) acc2[m] = 0ull;
#pragma unroll
    for (int k = 0; k < HC1; k++) {
        F4U2 xa, xb;
        xa.f4 = *(float4*)&xst[k][rb];
        xb.f4 = *(float4*)&xst[k][rb + 4];
        float wv = Ws[k][lane];
        u64 wd;
        PACK2(wd, wv, wv);
        FMA_X2(acc2[0], xa.u[0], wd, acc2[0]);
        FMA_X2(acc2[1], xa.u[1], wd, acc2[1]);
        FMA_X2(acc2[2], xb.u[0], wd, acc2[2]);
        FMA_X2(acc2[3], xb.u[1], wd, acc2[3]);
    }
    float acc[8];
#pragma unroll
    for (int m = 0; m < 4; m++) UNPACK2(acc[2 * m], acc[2 * m + 1], acc2[m]);

    float av = asrc[lane], bv = adst[lane];
#pragma unroll
    for (int r = 0; r < 8; r++) {
        int row = row0 + rb + r;
        if (row < NN) g_h2h[row * OUTC + lane] = __float2half_rn(acc[r]);
        float ps = acc[r] * av;
        float pd = acc[r] * bv;
#pragma unroll
        for (int off = 16; off >= 1; off >>= 1) {
            ps += __shfl_down_sync(0xffffffffu, ps, off);
            pd += __shfl_down_sync(0xffffffffu, pd, off);
        }
        if (lane == 0 && row < NN) {
            g_al_src2[row] = ps;
            g_al_dst2[row] = pd;
        }
    }
}

// ---------------- fused agg2: warp per dst node ----------------
__global__ void agg2_kernel(float* __restrict__ dout, const float* __restrict__ b2) {
    int gid = blockIdx.x * blockDim.x + threadIdx.x;
    int d = gid >> 5;
    int lane = gid & 31;
    if (d >= NN) return;
    const float* __restrict__ als = g_al_src2;
    const int* __restrict__ esrc = g_esrc;
    const __half* __restrict__ h2p = g_h2h;
    float ad2 = g_al_dst2[d];
    int j0 = g_off[d], j1 = g_off[d + 1];
    float acc = 0.f, den = 0.f;
    int j = j0;
    for (; j + 3 < j1; j += 4) {
        int s0 = esrc[j],     s1 = esrc[j + 1];
        int s2 = esrc[j + 2], s3 = esrc[j + 3];
        float as0 = als[s0], as1 = als[s1], as2 = als[s2], as3 = als[s3];
        float v0 = __half2float(h2p[s0 * OUTC + lane]);
        float v1 = __half2float(h2p[s1 * OUTC + lane]);
        float v2 = __half2float(h2p[s2 * OUTC + lane]);
        float v3 = __half2float(h2p[s3 * OUTC + lane]);
        float w0 = __expf(leaky(as0 + ad2));
        float w1 = __expf(leaky(as1 + ad2));
        float w2 = __expf(leaky(as2 + ad2));
        float w3 = __expf(leaky(as3 + ad2));
        den += (w0 + w1) + (w2 + w3);
        acc += w0 * v0 + w1 * v1 + w2 * v2 + w3 * v3;
    }
    for (; j < j1; j++) {
        int s0 = esrc[j];
        float w0 = __expf(leaky(als[s0] + ad2));
        den += w0;
        acc += w0 * __half2float(h2p[s0 * OUTC + lane]);
    }
    dout[d * OUTC + lane] = acc / den + b2[lane];
}

// ---------------- launch ----------------
extern "C" void kernel_launch(void* const* d_in, const int* in_sizes, int n_in,
                              void* d_out, int out_size) {
    const float* x        = (const float*)d_in[0];
    const int*   ei       = (const int*)d_in[1];
    const float* W1       = (const float*)d_in[2];
    const float* att_src1 = (const float*)d_in[3];
    const float* att_dst1 = (const float*)d_in[4];
    const float* b1       = (const float*)d_in[5];
    const float* W2       = (const float*)d_in[6];
    const float* att_src2 = (const float*)d_in[7];
    const float* att_dst2 = (const float*)d_in[8];
    const float* b2       = (const float*)d_in[9];
    float* dout = (float*)d_out;

    const int T = 256;
    init_kernel<<<(NN + T - 1) / T, T>>>(ei);
    hist_kernel<<<(EETOT + T - 1) / T, T>>>(ei);
    scan1_kernel<<<NB_SCAN, 1024>>>();
    scan2_kernel<<<1, 128>>>();
    scan3_kernel<<<(NN + T - 1) / T, T>>>();
    scatter_kernel<<<(EETOT + T - 1) / T, T>>>(ei);

    gemm1_kernel<<<(NN + G1_ROWS - 1) / G1_ROWS, 256>>>(x, W1, att_src1, att_dst1);
    agg1_kernel<<<(NN * 32 + T - 1) / T, T>>>(b1);

    gemm2_kernel<<<(NN + G2_ROWS - 1) / G2_ROWS, 256>>>(W2, att_src2, att_dst2);
    agg2_kernel<<<(NN * 32 + T - 1) / T, T>>>(dout, b2);
}

// round 6
// speedup vs baseline: 4.2396x; 1.0457x over previous
#include <cuda_runtime.h>
#include <cuda_fp16.h>
#include <math.h>

// ---------------- problem constants ----------------
#define NN   100000
#define EE0  1600000            // raw edges
#define EETOT (EE0 + NN)        // + self loops
#define C1   64                 // in channels
#define H1   4                  // heads layer1
#define HC1  128                // H1*D1
#define OUTC 32                 // layer2 out channels
#define NB_SCAN 98              // ceil(NN/1024)

typedef unsigned long long u64;
#define FMA_X2(d, a, b, c) \
    asm("fma.rn.f32x2 %0, %1, %2, %3;" : "=l"(d) : "l"(a), "l"(b), "l"(c))
#define PACK2(d, lo, hi) \
    asm("mov.b64 %0, {%1, %2};" : "=l"(d) : "f"(lo), "f"(hi))
#define UNPACK2(lo, hi, s) \
    asm("mov.b64 {%0, %1}, %2;" : "=f"(lo), "=f"(hi) : "l"(s))

union F4U2 { float4 f4; u64 u[2]; };

// ---------------- scratch (device globals; no allocation) ----------------
__device__ __half g_h1h[NN * HC1];      // layer1 features (fp16, gather-only)
__device__ __half g_out1h[NN * HC1];    // elu(agg1 + b1) (fp16, gemm2 input)
__device__ float  g_al_src1[NN * H1];
__device__ float  g_al_dst1[NN * H1];

__device__ __half g_h2h[NN * OUTC];     // layer2 features (fp16, gather-only)
__device__ float  g_al_src2[NN];
__device__ float  g_al_dst2[NN];

// CSR build: g_degx = [deg[NN], ticket, flag]  (zeroed by one memset node)
__device__ int g_degx[NN + 2];
__device__ int g_cursor[NN];
__device__ int g_bsum[NB_SCAN];
__device__ int g_boff[NB_SCAN];
__device__ int g_off[NN + 1];
__device__ int g_esrc[EETOT];

// ---------------- helpers ----------------
__device__ __forceinline__ float leaky(float v) { return v > 0.f ? v : 0.2f * v; }

// int64 little-endian edges => int32 view has zero high words (indices < 2^31)
__device__ __forceinline__ int detect_is64(const int* __restrict__ ei) {
    int zeros = 0;
#pragma unroll
    for (int k = 0; k < 16; k++) zeros += (ei[2 * k + 1] == 0);
    return zeros == 16;
}

__device__ __forceinline__ void h4load(const __half* p, float& f0, float& f1,
                                       float& f2, float& f3) {
    uint2 u = *reinterpret_cast<const uint2*>(p);
    __half2 a = *reinterpret_cast<__half2*>(&u.x);
    __half2 b = *reinterpret_cast<__half2*>(&u.y);
    float2 fa = __half22float2(a), fb = __half22float2(b);
    f0 = fa.x; f1 = fa.y; f2 = fb.x; f3 = fb.y;
}

// ---------------- GEMM1 + fused logits1 + fused dst histogram ----------------
// h1[N,128] = x[N,64] @ W1[64,128]; al_src1/al_dst1[N,4]; g_deg histogram
#define G1_ROWS 64
__global__ __launch_bounds__(256) void gemm1_kernel(const float* __restrict__ x,
                                                    const float* __restrict__ W,
                                                    const float* __restrict__ asrc,
                                                    const float* __restrict__ adst,
                                                    const int* __restrict__ ei) {
    __shared__ float xst[C1][G1_ROWS];   // [k][row] 16 KB
    __shared__ float Ws[C1][HC1];        // 32 KB
    __shared__ int sh_is64;
    int tid = threadIdx.x;
    int row0 = blockIdx.x * G1_ROWS;
    if (tid == 0) sh_is64 = detect_is64(ei);

    const float4* W4 = (const float4*)W;
    float4* Ws4 = (float4*)Ws;
#pragma unroll
    for (int i = 0; i < 8; i++) Ws4[tid + 256 * i] = W4[tid + 256 * i];
#pragma unroll
    for (int i = 0; i < 4; i++) {
        int idx = tid + 256 * i;          // float4 idx; 16 per row
        int r = idx >> 4, k4 = idx & 15;
        int row = row0 + r;
        float4 v = make_float4(0.f, 0.f, 0.f, 0.f);
        if (row < NN) v = *(const float4*)&x[row * C1 + k4 * 4];
        xst[k4 * 4 + 0][r] = v.x; xst[k4 * 4 + 1][r] = v.y;
        xst[k4 * 4 + 2][r] = v.z; xst[k4 * 4 + 3][r] = v.w;
    }
    __syncthreads();

    int lane = tid & 31, w = tid >> 5;
    int rb = w * 8;
    u64 acc2[4][4];                     // [row-pair][col]
#pragma unroll
    for (int m = 0; m < 4; m++)
#pragma unroll
        for (int c = 0; c < 4; c++) acc2[m][c] = 0ull;

#pragma unroll
    for (int k = 0; k < C1; k++) {
        F4U2 xa, xb;
        xa.f4 = *(float4*)&xst[k][rb];
        xb.f4 = *(float4*)&xst[k][rb + 4];
        float4 wv = *(float4*)&Ws[k][lane * 4];
        u64 wd[4];
        PACK2(wd[0], wv.x, wv.x); PACK2(wd[1], wv.y, wv.y);
        PACK2(wd[2], wv.z, wv.z); PACK2(wd[3], wv.w, wv.w);
        u64 xp[4] = {xa.u[0], xa.u[1], xb.u[0], xb.u[1]};
#pragma unroll
        for (int m = 0; m < 4; m++) {
            FMA_X2(acc2[m][0], xp[m], wd[0], acc2[m][0]);
            FMA_X2(acc2[m][1], xp[m], wd[1], acc2[m][1]);
            FMA_X2(acc2[m][2], xp[m], wd[2], acc2[m][2]);
            FMA_X2(acc2[m][3], xp[m], wd[3], acc2[m][3]);
        }
    }

    float acc[8][4];
#pragma unroll
    for (int m = 0; m < 4; m++)
#pragma unroll
        for (int c = 0; c < 4; c++)
            UNPACK2(acc[2 * m][c], acc[2 * m + 1][c], acc2[m][c]);

    float4 av = *(const float4*)&asrc[lane * 4];
    float4 bv = *(const float4*)&adst[lane * 4];
    int head = lane >> 3;
#pragma unroll
    for (int r = 0; r < 8; r++) {
        int row = row0 + rb + r;
        if (row < NN) {
            __half2 p0 = __floats2half2_rn(acc[r][0], acc[r][1]);
            __half2 p1 = __floats2half2_rn(acc[r][2], acc[r][3]);
            uint2 u;
            u.x = *reinterpret_cast<unsigned*>(&p0);
            u.y = *reinterpret_cast<unsigned*>(&p1);
            *reinterpret_cast<uint2*>(&g_h1h[row * HC1 + lane * 4]) = u;
        }
        float ps = acc[r][0] * av.x + acc[r][1] * av.y + acc[r][2] * av.z + acc[r][3] * av.w;
        float pd = acc[r][0] * bv.x + acc[r][1] * bv.y + acc[r][2] * bv.z + acc[r][3] * bv.w;
#pragma unroll
        for (int off = 4; off >= 1; off >>= 1) {
            ps += __shfl_down_sync(0xffffffffu, ps, off);
            pd += __shfl_down_sync(0xffffffffu, pd, off);
        }
        if ((lane & 7) == 0 && row < NN) {
            g_al_src1[row * H1 + head] = ps;
            g_al_dst1[row * H1 + head] = pd;
        }
    }

    // ---- fused dst histogram (memory-bound; hides under FFMA work) ----
    int is64 = sh_is64;
    int stride = gridDim.x * blockDim.x;
    for (int e = blockIdx.x * blockDim.x + tid; e < EETOT; e += stride) {
        int d;
        if (e >= EE0) d = e - EE0;
        else d = is64 ? ei[2 * (EE0 + e)] : ei[EE0 + e];
        atomicAdd(&g_degx[d], 1);
    }
}

// ---------------- fused scan: one kernel, grid-wide handoff ----------------
// 98 blocks x 1024 threads (all resident in one wave => spin is safe)
__global__ __launch_bounds__(1024) void scan_kernel() {
    __shared__ int warp_tot[32];
    __shared__ int block_base;
    int t = threadIdx.x;
    int i = blockIdx.x * 1024 + t;
    int lane = t & 31, w = t >> 5;
    int deg = (i < NN) ? g_degx[i] : 0;
    int sum = deg;
#pragma unroll
    for (int o = 1; o < 32; o <<= 1) {
        int u = __shfl_up_sync(0xffffffffu, sum, o);
        if (lane >= o) sum += u;
    }
    if (lane == 31) warp_tot[w] = sum;
    __syncthreads();
    if (w == 0) {
        int s = warp_tot[lane];
#pragma unroll
        for (int o = 1; o < 32; o <<= 1) {
            int u = __shfl_up_sync(0xffffffffu, s, o);
            if (lane >= o) s += u;
        }
        warp_tot[lane] = s;
    }
    __syncthreads();
    int wbase = (w > 0) ? warp_tot[w - 1] : 0;
    int inc = wbase + sum;              // inclusive scan within block
    if (t == 1023) g_bsum[blockIdx.x] = inc;
    __syncthreads();                    // bsum written before ticket

    // grid-wide handoff: last-arriving block scans the 98 block sums
    if (w == 0) {
        int ticket = 0;
        if (lane == 0) {
            __threadfence();
            ticket = atomicAdd(&g_degx[NN], 1);       // ticket counter
        }
        ticket = __shfl_sync(0xffffffffu, ticket, 0);
        if (ticket == NB_SCAN - 1) {
            // warp-scan of NB_SCAN block totals (4 chunks of 32 with carry)
            int carry = 0;
#pragma unroll
            for (int c = 0; c < 4; c++) {
                int idx = c * 32 + lane;
                int v = (idx < NB_SCAN) ? g_bsum[idx] : 0;
                int s = v;
#pragma unroll
                for (int o = 1; o < 32; o <<= 1) {
                    int u = __shfl_up_sync(0xffffffffu, s, o);
                    if (lane >= o) s += u;
                }
                if (idx < NB_SCAN) g_boff[idx] = carry + s - v;   // exclusive
                carry += __shfl_sync(0xffffffffu, s, 31);
            }
            __threadfence();
            if (lane == 0) atomicExch(&g_degx[NN + 1], 1);        // flag
        }
        if (lane == 0) {
            while (atomicAdd(&g_degx[NN + 1], 0) == 0) { }
            __threadfence();
            block_base = g_boff[blockIdx.x];
        }
    }
    __syncthreads();
    int base = block_base;
    if (i == 0) g_off[0] = 0;
    if (i < NN) {
        int end = base + inc;
        g_off[i + 1] = end;
        g_cursor[i] = end - deg;        // start offset; scatter bumps this
    }
}

__global__ void scatter_kernel(const int* __restrict__ ei) {
    __shared__ int sh_is64;
    if (threadIdx.x == 0) sh_is64 = detect_is64(ei);
    __syncthreads();
    int e = blockIdx.x * blockDim.x + threadIdx.x;
    if (e >= EETOT) return;
    int is64 = sh_is64;
    int s, d;
    if (e >= EE0) { s = d = e - EE0; }
    else if (is64) { s = ei[2 * e]; d = ei[2 * (EE0 + e)]; }
    else           { s = ei[e];     d = ei[EE0 + e]; }
    int pos = atomicAdd(&g_cursor[d], 1);
    g_esrc[pos] = s;
}

// ---------------- fused agg1: warp per dst node, CSR, no atomics ----------------
__global__ void agg1_kernel(const float* __restrict__ b1) {
    int gid = blockIdx.x * blockDim.x + threadIdx.x;
    int d = gid >> 5;
    int lane = gid & 31;
    if (d >= NN) return;
    int h = lane >> 3;
    const float* __restrict__ als = g_al_src1;
    const int* __restrict__ esrc = g_esrc;
    const __half* __restrict__ h1p = g_h1h;
    float adh = g_al_dst1[d * H1 + h];
    int j0 = g_off[d], j1 = g_off[d + 1];
    float4 acc = make_float4(0.f, 0.f, 0.f, 0.f);
    float den = 0.f;
    int j = j0;
    for (; j + 3 < j1; j += 4) {
        int s0 = esrc[j],     s1 = esrc[j + 1];
        int s2 = esrc[j + 2], s3 = esrc[j + 3];
        float as0 = als[s0 * H1 + h];
        float as1 = als[s1 * H1 + h];
        float as2 = als[s2 * H1 + h];
        float as3 = als[s3 * H1 + h];
        float a0, a1, a2, a3, c0, c1, c2, c3;
        float e0, e1, e2, e3, f0, f1, f2, f3;
        h4load(&h1p[s0 * HC1 + lane * 4], a0, a1, a2, a3);
        h4load(&h1p[s1 * HC1 + lane * 4], c0, c1, c2, c3);
        h4load(&h1p[s2 * HC1 + lane * 4], e0, e1, e2, e3);
        h4load(&h1p[s3 * HC1 + lane * 4], f0, f1, f2, f3);
        float w0 = __expf(leaky(as0 + adh));
        float w1 = __expf(leaky(as1 + adh));
        float w2 = __expf(leaky(as2 + adh));
        float w3 = __expf(leaky(as3 + adh));
        den += (w0 + w1) + (w2 + w3);
        acc.x += w0 * a0 + w1 * c0 + w2 * e0 + w3 * f0;
        acc.y += w0 * a1 + w1 * c1 + w2 * e1 + w3 * f1;
        acc.z += w0 * a2 + w1 * c2 + w2 * e2 + w3 * f2;
        acc.w += w0 * a3 + w1 * c3 + w2 * e3 + w3 * f3;
    }
    for (; j < j1; j++) {
        int s0 = esrc[j];
        float as0 = als[s0 * H1 + h];
        float a0, a1, a2, a3;
        h4load(&h1p[s0 * HC1 + lane * 4], a0, a1, a2, a3);
        float w0 = __expf(leaky(as0 + adh));
        den += w0;
        acc.x += w0 * a0; acc.y += w0 * a1;
        acc.z += w0 * a2; acc.w += w0 * a3;
    }
    float inv = 1.f / den;      // self-loop guarantees den > 0
    float4 b = *reinterpret_cast<const float4*>(&b1[lane * 4]);
    float4 o;
    o.x = acc.x * inv + b.x; o.y = acc.y * inv + b.y;
    o.z = acc.z * inv + b.z; o.w = acc.w * inv + b.w;
    o.x = o.x > 0.f ? o.x : expm1f(o.x);
    o.y = o.y > 0.f ? o.y : expm1f(o.y);
    o.z = o.z > 0.f ? o.z : expm1f(o.z);
    o.w = o.w > 0.f ? o.w : expm1f(o.w);
    __half2 p0 = __floats2half2_rn(o.x, o.y);
    __half2 p1 = __floats2half2_rn(o.z, o.w);
    uint2 u;
    u.x = *reinterpret_cast<unsigned*>(&p0);
    u.y = *reinterpret_cast<unsigned*>(&p1);
    *reinterpret_cast<uint2*>(&g_out1h[d * HC1 + lane * 4]) = u;
}

// ---------------- GEMM2 + fused logits2 ----------------
// h2[N,32] = out1[N,128] @ W2[128,32]
#define G2_ROWS 64
__global__ __launch_bounds__(256) void gemm2_kernel(const float* __restrict__ W2,
                                                    const float* __restrict__ asrc,
                                                    const float* __restrict__ adst) {
    __shared__ float xst[HC1][G2_ROWS];  // 32 KB
    __shared__ float Ws[HC1][OUTC];      // 16 KB
    int tid = threadIdx.x;
    int row0 = blockIdx.x * G2_ROWS;

    const float4* W4 = (const float4*)W2;
    float4* Ws4 = (float4*)Ws;
#pragma unroll
    for (int i = 0; i < 4; i++) Ws4[tid + 256 * i] = W4[tid + 256 * i];
#pragma unroll
    for (int i = 0; i < 4; i++) {
        int idx = tid + 256 * i;          // uint4 (8 halves) idx; 16 per row
        int r = idx >> 4, k8 = idx & 15;
        int row = row0 + r;
        uint4 v = make_uint4(0u, 0u, 0u, 0u);
        if (row < NN) v = *(const uint4*)&g_out1h[row * HC1 + k8 * 8];
        const unsigned uu[4] = {v.x, v.y, v.z, v.w};
#pragma unroll
        for (int q = 0; q < 4; q++) {
            __half2 hh = *reinterpret_cast<const __half2*>(&uu[q]);
            float2 ff = __half22float2(hh);
            xst[k8 * 8 + q * 2 + 0][r] = ff.x;
            xst[k8 * 8 + q * 2 + 1][r] = ff.y;
        }
    }
    __syncthreads();

    int lane = tid & 31, w = tid >> 5;
    int rb = w * 8;
    u64 acc2[4];
#pragma unroll
    for (int m = 0; m < 4; m++) acc2[m] = 0ull;
#pragma unroll
    for (int k = 0; k < HC1; k++) {
        F4U2 xa, xb;
        xa.f4 = *(float4*)&xst[k][rb];
        xb.f4 = *(float4*)&xst[k][rb + 4];
        float wv = Ws[k][lane];
        u64 wd;
        PACK2(wd, wv, wv);
        FMA_X2(acc2[0], xa.u[0], wd, acc2[0]);
        FMA_X2(acc2[1], xa.u[1], wd, acc2[1]);
        FMA_X2(acc2[2], xb.u[0], wd, acc2[2]);
        FMA_X2(acc2[3], xb.u[1], wd, acc2[3]);
    }
    float acc[8];
#pragma unroll
    for (int m = 0; m < 4; m++) UNPACK2(acc[2 * m], acc[2 * m + 1], acc2[m]);

    float av = asrc[lane], bv = adst[lane];
#pragma unroll
    for (int r = 0; r < 8; r++) {
        int row = row0 + rb + r;
        if (row < NN) g_h2h[row * OUTC + lane] = __float2half_rn(acc[r]);
        float ps = acc[r] * av;
        float pd = acc[r] * bv;
#pragma unroll
        for (int off = 16; off >= 1; off >>= 1) {
            ps += __shfl_down_sync(0xffffffffu, ps, off);
            pd += __shfl_down_sync(0xffffffffu, pd, off);
        }
        if (lane == 0 && row < NN) {
            g_al_src2[row] = ps;
            g_al_dst2[row] = pd;
        }
    }
}

// ---------------- fused agg2: warp per dst node ----------------
__global__ void agg2_kernel(float* __restrict__ dout, const float* __restrict__ b2) {
    int gid = blockIdx.x * blockDim.x + threadIdx.x;
    int d = gid >> 5;
    int lane = gid & 31;
    if (d >= NN) return;
    const float* __restrict__ als = g_al_src2;
    const int* __restrict__ esrc = g_esrc;
    const __half* __restrict__ h2p = g_h2h;
    float ad2 = g_al_dst2[d];
    int j0 = g_off[d], j1 = g_off[d + 1];
    float acc = 0.f, den = 0.f;
    int j = j0;
    for (; j + 3 < j1; j += 4) {
        int s0 = esrc[j],     s1 = esrc[j + 1];
        int s2 = esrc[j + 2], s3 = esrc[j + 3];
        float as0 = als[s0], as1 = als[s1], as2 = als[s2], as3 = als[s3];
        float v0 = __half2float(h2p[s0 * OUTC + lane]);
        float v1 = __half2float(h2p[s1 * OUTC + lane]);
        float v2 = __half2float(h2p[s2 * OUTC + lane]);
        float v3 = __half2float(h2p[s3 * OUTC + lane]);
        float w0 = __expf(leaky(as0 + ad2));
        float w1 = __expf(leaky(as1 + ad2));
        float w2 = __expf(leaky(as2 + ad2));
        float w3 = __expf(leaky(as3 + ad2));
        den += (w0 + w1) + (w2 + w3);
        acc += w0 * v0 + w1 * v1 + w2 * v2 + w3 * v3;
    }
    for (; j < j1; j++) {
        int s0 = esrc[j];
        float w0 = __expf(leaky(als[s0] + ad2));
        den += w0;
        acc += w0 * __half2float(h2p[s0 * OUTC + lane]);
    }
    dout[d * OUTC + lane] = acc / den + b2[lane];
}

// ---------------- launch ----------------
extern "C" void kernel_launch(void* const* d_in, const int* in_sizes, int n_in,
                              void* d_out, int out_size) {
    const float* x        = (const float*)d_in[0];
    const int*   ei       = (const int*)d_in[1];
    const float* W1       = (const float*)d_in[2];
    const float* att_src1 = (const float*)d_in[3];
    const float* att_dst1 = (const float*)d_in[4];
    const float* b1       = (const float*)d_in[5];
    const float* W2       = (const float*)d_in[6];
    const float* att_src2 = (const float*)d_in[7];
    const float* att_dst2 = (const float*)d_in[8];
    const float* b2       = (const float*)d_in[9];
    float* dout = (float*)d_out;

    const int T = 256;
    void* degx_ptr = nullptr;
    cudaGetSymbolAddress(&degx_ptr, g_degx);
    cudaMemsetAsync(degx_ptr, 0, (NN + 2) * sizeof(int));

    gemm1_kernel<<<(NN + G1_ROWS - 1) / G1_ROWS, 256>>>(x, W1, att_src1, att_dst1, ei);
    scan_kernel<<<NB_SCAN, 1024>>>();
    scatter_kernel<<<(EETOT + T - 1) / T, T>>>(ei);
    agg1_kernel<<<(NN * 32 + T - 1) / T, T>>>(b1);

    gemm2_kernel<<<(NN + G2_ROWS - 1) / G2_ROWS, 256>>>(W2, att_src2, att_dst2);
    agg2_kernel<<<(NN * 32 + T - 1) / T, T>>>(dout, b2);
}